// round 2
// baseline (speedup 1.0000x reference)
#include <cuda_runtime.h>
#include <math.h>

#define SQ  4096   // H*W
#define CIN 256    // C
#define CH  128    // C/2
#define NB  8      // batch

// Scratch (no allocations allowed -> __device__ globals)
__device__ float g_Q [(size_t)NB * CH * SQ];   // theta_x  [n][o][s]
__device__ float g_K [(size_t)NB * CH * SQ];   // phi_x    [n][o][s]
__device__ float g_xT[(size_t)NB * SQ * CIN];  // x transposed [n][s][c]  (V)

// ---------------------------------------------------------------------------
// Kernel 1: 1x1-conv projections (theta_x, phi_x) + transpose x into V layout.
// Grid (64 s-tiles, 8 batches), 256 threads. Each block: 64 s x 128 o x 2 mats.
// ---------------------------------------------------------------------------
__global__ __launch_bounds__(256) void proj_kernel(const float* __restrict__ x,
                                                   const float* __restrict__ tw,
                                                   const float* __restrict__ pw)
{
    const int n  = blockIdx.y;
    const int s0 = blockIdx.x * 64;
    const int tid = threadIdx.x;
    const int ts = tid & 15;      // s micro-tile index (4 s each)
    const int to = tid >> 4;      // o micro-tile index (8 o each)

    __shared__ float xs [32][68];   // [cc][ss]  pad: 16B-aligned rows
    __shared__ float wts[128][33];  // theta_w tile [o][cc]
    __shared__ float wps[128][33];  // phi_w tile

    float qa[8][4], ka[8][4];
#pragma unroll
    for (int k = 0; k < 8; k++)
#pragma unroll
        for (int i = 0; i < 4; i++) { qa[k][i] = 0.f; ka[k][i] = 0.f; }

    const float* xb = x + (size_t)n * CIN * SQ;

    for (int c0 = 0; c0 < CIN; c0 += 32) {
        __syncthreads();
        // x tile [32 c][64 s], coalesced along s
#pragma unroll
        for (int k = 0; k < 8; k++) {
            int idx = tid + 256 * k;          // 0..2047
            int cc = idx >> 6, ss = idx & 63;
            xs[cc][ss] = xb[(size_t)(c0 + cc) * SQ + s0 + ss];
        }
        // weight tiles [128 o][32 c], coalesced along c
#pragma unroll
        for (int k = 0; k < 16; k++) {
            int idx = tid + 256 * k;          // 0..4095
            int o = idx >> 5, cc = idx & 31;
            wts[o][cc] = tw[o * CIN + c0 + cc];
            wps[o][cc] = pw[o * CIN + c0 + cc];
        }
        __syncthreads();
        // emit transposed x (V layout), coalesced along c
#pragma unroll
        for (int k = 0; k < 8; k++) {
            int idx = tid + 256 * k;
            int ss = idx >> 5, cc = idx & 31;
            g_xT[((size_t)n * SQ + s0 + ss) * CIN + c0 + cc] = xs[cc][ss];
        }
        // FMA: 8 o x 4 s per thread per matrix
#pragma unroll
        for (int cc = 0; cc < 32; cc++) {
            float4 xv = *(const float4*)&xs[cc][ts * 4];
            float xr[4] = { xv.x, xv.y, xv.z, xv.w };
#pragma unroll
            for (int k = 0; k < 8; k++) {
                float twv = wts[to * 8 + k][cc];
                float pwv = wps[to * 8 + k][cc];
#pragma unroll
                for (int i = 0; i < 4; i++) {
                    qa[k][i] = fmaf(twv, xr[i], qa[k][i]);
                    ka[k][i] = fmaf(pwv, xr[i], ka[k][i]);
                }
            }
        }
    }
    // store Q,K as [n][o][s]
#pragma unroll
    for (int k = 0; k < 8; k++) {
        int o = to * 8 + k;
        float4 qv = make_float4(qa[k][0], qa[k][1], qa[k][2], qa[k][3]);
        float4 kv = make_float4(ka[k][0], ka[k][1], ka[k][2], ka[k][3]);
        *(float4*)&g_Q[((size_t)n * CH + o) * SQ + s0 + ts * 4] = qv;
        *(float4*)&g_K[((size_t)n * CH + o) * SQ + s0 + ts * 4] = kv;
    }
}

// ---------------------------------------------------------------------------
// Kernel 2: flash attention, fp32. BM=BN=64, d=128, dv=256.
// Grid (64 q-tiles, 8 batches), 256 threads (16x16), ~145 KB dyn smem.
//   S = Q^T K  (from g_Q/g_K, both stored [d][s] per batch -> LDS.128 reads)
//   online softmax, O += P V with V = xT tile, epilogue: out = x + O / l
// ---------------------------------------------------------------------------
__global__ __launch_bounds__(256) void flash_kernel(const float* __restrict__ x,
                                                    float* __restrict__ out)
{
    extern __shared__ float sm[];
    float* Qs = sm;                    // [128][64]
    float* Ks = Qs + 128 * 64;         // [128][64]
    float* Ps = Ks + 128 * 64;         // [64][68]  (pad 68)
    float* Vs = Ps + 64 * 68;          // [64][256] (reused as O staging)

    const int n  = blockIdx.y;
    const int s0 = blockIdx.x * 64;
    const int tid = threadIdx.x;
    const int tx = tid & 15;           // key cols (QK) / value col group (PV)
    const int ty = tid >> 4;           // query rows (4 each)

    // load Q tile [128 d][64 s], coalesced
#pragma unroll
    for (int k = 0; k < 8; k++) {
        int idx = tid + 256 * k;                  // 2048 float4
        int o = idx >> 4, col = (idx & 15) * 4;
        *(float4*)&Qs[o * 64 + col] =
            *(const float4*)&g_Q[((size_t)n * CH + o) * SQ + s0 + col];
    }

    float m[4], l[4], o_[4][16];
#pragma unroll
    for (int i = 0; i < 4; i++) {
        m[i] = -1e30f; l[i] = 0.f;
#pragma unroll
        for (int k = 0; k < 16; k++) o_[i][k] = 0.f;
    }

    for (int t0 = 0; t0 < SQ; t0 += 64) {
        __syncthreads();   // prev iter's Ps/Vs reads done
        // K tile [128 d][64 t]
#pragma unroll
        for (int k = 0; k < 8; k++) {
            int idx = tid + 256 * k;
            int o = idx >> 4, col = (idx & 15) * 4;
            *(float4*)&Ks[o * 64 + col] =
                *(const float4*)&g_K[((size_t)n * CH + o) * SQ + t0 + col];
        }
        // V tile [64 t][256 c]
#pragma unroll
        for (int k = 0; k < 16; k++) {
            int idx = tid + 256 * k;                  // 4096 float4
            int t = idx >> 6, c = (idx & 63) * 4;
            *(float4*)&Vs[t * 256 + c] =
                *(const float4*)&g_xT[((size_t)n * SQ + t0 + t) * CIN + c];
        }
        __syncthreads();

        // --- S = Q^T K  (4x4 per thread) ---
        float acc[4][4];
#pragma unroll
        for (int i = 0; i < 4; i++)
#pragma unroll
            for (int j = 0; j < 4; j++) acc[i][j] = 0.f;

#pragma unroll 8
        for (int kk = 0; kk < 128; kk++) {
            float4 a = *(const float4*)&Qs[kk * 64 + ty * 4];
            float4 b = *(const float4*)&Ks[kk * 64 + tx * 4];
            float ar[4] = { a.x, a.y, a.z, a.w };
            float br[4] = { b.x, b.y, b.z, b.w };
#pragma unroll
            for (int i = 0; i < 4; i++)
#pragma unroll
                for (int j = 0; j < 4; j++)
                    acc[i][j] = fmaf(ar[i], br[j], acc[i][j]);
        }

        // --- online softmax (rows = ty*4+i, reduce over 16 tx lanes) ---
#pragma unroll
        for (int i = 0; i < 4; i++) {
            float tm = fmaxf(fmaxf(acc[i][0], acc[i][1]),
                             fmaxf(acc[i][2], acc[i][3]));
#pragma unroll
            for (int off = 8; off > 0; off >>= 1)
                tm = fmaxf(tm, __shfl_xor_sync(0xffffffffu, tm, off));
            float mn = fmaxf(m[i], tm);
            float al = __expf(m[i] - mn);
            float rs = 0.f;
#pragma unroll
            for (int j = 0; j < 4; j++) {
                acc[i][j] = __expf(acc[i][j] - mn);
                rs += acc[i][j];
            }
#pragma unroll
            for (int off = 8; off > 0; off >>= 1)
                rs += __shfl_xor_sync(0xffffffffu, rs, off);
            l[i] = l[i] * al + rs;
            m[i] = mn;
#pragma unroll
            for (int k = 0; k < 16; k++) o_[i][k] *= al;
            // P row -> shared [s][t] (float4, aligned: 68*4B = 272B rows)
            *(float4*)&Ps[(ty * 4 + i) * 68 + tx * 4] =
                make_float4(acc[i][0], acc[i][1], acc[i][2], acc[i][3]);
        }
        __syncthreads();

        // --- O += P V : 4 rows x (4 groups of 4 cols) per thread ---
#pragma unroll 2
        for (int tt = 0; tt < 64; tt++) {
            float a0 = Ps[(ty * 4 + 0) * 68 + tt];
            float a1 = Ps[(ty * 4 + 1) * 68 + tt];
            float a2 = Ps[(ty * 4 + 2) * 68 + tt];
            float a3 = Ps[(ty * 4 + 3) * 68 + tt];
            float ar[4] = { a0, a1, a2, a3 };
#pragma unroll
            for (int kb = 0; kb < 4; kb++) {
                float4 b = *(const float4*)&Vs[tt * 256 + tx * 4 + 64 * kb];
                float br[4] = { b.x, b.y, b.z, b.w };
#pragma unroll
                for (int i = 0; i < 4; i++)
#pragma unroll
                    for (int j = 0; j < 4; j++)
                        o_[i][kb * 4 + j] = fmaf(ar[i], br[j], o_[i][kb * 4 + j]);
            }
        }
    }
    __syncthreads();   // all PV reads of Vs done -> reuse Vs as O staging

    // normalize and stage O[s][c] into shared
#pragma unroll
    for (int i = 0; i < 4; i++) {
        float inv = 1.0f / l[i];
#pragma unroll
        for (int k = 0; k < 16; k++) o_[i][k] *= inv;
#pragma unroll
        for (int kb = 0; kb < 4; kb++)
            *(float4*)&Vs[(ty * 4 + i) * 256 + tx * 4 + 64 * kb] =
                make_float4(o_[i][kb * 4 + 0], o_[i][kb * 4 + 1],
                            o_[i][kb * 4 + 2], o_[i][kb * 4 + 3]);
    }
    __syncthreads();

    // residual add, coalesced along s: thread tid owns channel c = tid
    const int c = tid;
    const float* xb = x   + ((size_t)n * CIN + c) * SQ + s0;
    float*       ob = out + ((size_t)n * CIN + c) * SQ + s0;
#pragma unroll
    for (int ss = 0; ss < 64; ss += 4) {
        float4 xv = *(const float4*)&xb[ss];
        float4 r;
        r.x = xv.x + Vs[(ss + 0) * 256 + c];
        r.y = xv.y + Vs[(ss + 1) * 256 + c];
        r.z = xv.z + Vs[(ss + 2) * 256 + c];
        r.w = xv.w + Vs[(ss + 3) * 256 + c];
        *(float4*)&ob[ss] = r;
    }
}

// ---------------------------------------------------------------------------
extern "C" void kernel_launch(void* const* d_in, const int* in_sizes, int n_in,
                              void* d_out, int out_size)
{
    const float* x  = (const float*)d_in[0];   // [8,256,64,64]
    const float* tw = (const float*)d_in[1];   // [128,256]
    const float* pw = (const float*)d_in[2];   // [128,256]
    float* out = (float*)d_out;

    const int FLASH_SMEM = (128 * 64 + 128 * 64 + 64 * 68 + 64 * 256) * 4; // 148480 B
    cudaFuncSetAttribute(flash_kernel,
                         cudaFuncAttributeMaxDynamicSharedMemorySize, FLASH_SMEM);

    proj_kernel<<<dim3(64, 8), 256>>>(x, tw, pw);
    flash_kernel<<<dim3(64, 8), 256, FLASH_SMEM>>>(x, out);
}

// round 4
// speedup vs baseline: 2.4449x; 2.4449x over previous
#include <cuda_runtime.h>
#include <cuda_fp16.h>
#include <math.h>

#define SQ  4096   // H*W
#define CIN 256    // C
#define CH  128    // C/2
#define NB  8      // batch

// Scratch: Q,K projections as fp16 hi/lo pairs, layout [n][s][d] (ldmatrix-ready)
__device__ __half g_Qhi[(size_t)NB * SQ * CH];
__device__ __half g_Qlo[(size_t)NB * SQ * CH];
__device__ __half g_Khi[(size_t)NB * SQ * CH];
__device__ __half g_Klo[(size_t)NB * SQ * CH];

// ---------------------------------------------------------------------------
// helpers
// ---------------------------------------------------------------------------
union H2U { __half2 h; unsigned u; };

__device__ __forceinline__ unsigned h2u(__half2 v) {
    H2U c; c.h = v; return c.u;
}

__device__ __forceinline__ void cvt_hilo(float a, float b, __half2& hi, __half2& lo) {
    __half ha = __float2half_rn(a);
    __half hb = __float2half_rn(b);
    hi = __halves2half2(ha, hb);
    lo = __halves2half2(__float2half_rn(a - __half2float(ha)),
                        __float2half_rn(b - __half2float(hb)));
}

__device__ __forceinline__ void store4h2(__half* p, __half2 v0, __half2 v1,
                                         __half2 v2, __half2 v3) {
    uint4 u;
    u.x = h2u(v0); u.y = h2u(v1); u.z = h2u(v2); u.w = h2u(v3);
    *(uint4*)p = u;
}

__device__ __forceinline__ void ldsm_x4(unsigned* r, unsigned addr) {
    asm volatile("ldmatrix.sync.aligned.m8n8.x4.shared.b16 {%0,%1,%2,%3},[%4];\n"
                 : "=r"(r[0]), "=r"(r[1]), "=r"(r[2]), "=r"(r[3]) : "r"(addr));
}

__device__ __forceinline__ void ldsm_x2(unsigned* r, unsigned addr) {
    asm volatile("ldmatrix.sync.aligned.m8n8.x2.shared.b16 {%0,%1},[%2];\n"
                 : "=r"(r[0]), "=r"(r[1]) : "r"(addr));
}

__device__ __forceinline__ void mma16816(float* d, const unsigned* a, const unsigned* b) {
    asm volatile("mma.sync.aligned.m16n8k16.row.col.f32.f16.f16.f32 "
                 "{%0,%1,%2,%3},{%4,%5,%6,%7},{%8,%9},{%0,%1,%2,%3};\n"
                 : "+f"(d[0]), "+f"(d[1]), "+f"(d[2]), "+f"(d[3])
                 : "r"(a[0]), "r"(a[1]), "r"(a[2]), "r"(a[3]), "r"(b[0]), "r"(b[1]));
}

// ---------------------------------------------------------------------------
// Kernel 1: 1x1-conv projections -> fp16 hi/lo, layout [n][s][o].
// Grid (64 s-tiles, 8 batches), 256 threads.
// ---------------------------------------------------------------------------
__global__ __launch_bounds__(256) void proj_kernel(const float* __restrict__ x,
                                                   const float* __restrict__ tw,
                                                   const float* __restrict__ pw)
{
    const int n  = blockIdx.y;
    const int s0 = blockIdx.x * 64;
    const int tid = threadIdx.x;
    const int ts = tid & 15;      // s micro-tile index (4 s each)
    const int to = tid >> 4;      // o micro-tile index (8 o each)

    __shared__ float xs [32][68];
    __shared__ float wts[128][33];
    __shared__ float wps[128][33];

    float qa[8][4], ka[8][4];
#pragma unroll
    for (int k = 0; k < 8; k++) {
#pragma unroll
        for (int i = 0; i < 4; i++) { qa[k][i] = 0.f; ka[k][i] = 0.f; }
    }

    const float* xb = x + (size_t)n * CIN * SQ;

    for (int c0 = 0; c0 < CIN; c0 += 32) {
        __syncthreads();
#pragma unroll
        for (int k = 0; k < 8; k++) {
            int idx = tid + 256 * k;
            int cc = idx >> 6;
            int ss = idx & 63;
            xs[cc][ss] = xb[(size_t)(c0 + cc) * SQ + s0 + ss];
        }
#pragma unroll
        for (int k = 0; k < 16; k++) {
            int idx = tid + 256 * k;
            int o = idx >> 5;
            int cc = idx & 31;
            wts[o][cc] = tw[o * CIN + c0 + cc];
            wps[o][cc] = pw[o * CIN + c0 + cc];
        }
        __syncthreads();
#pragma unroll
        for (int cc = 0; cc < 32; cc++) {
            float4 xv = *(const float4*)&xs[cc][ts * 4];
            float xr[4];
            xr[0] = xv.x; xr[1] = xv.y; xr[2] = xv.z; xr[3] = xv.w;
#pragma unroll
            for (int k = 0; k < 8; k++) {
                float twv = wts[to * 8 + k][cc];
                float pwv = wps[to * 8 + k][cc];
#pragma unroll
                for (int i = 0; i < 4; i++) {
                    qa[k][i] = fmaf(twv, xr[i], qa[k][i]);
                    ka[k][i] = fmaf(pwv, xr[i], ka[k][i]);
                }
            }
        }
    }
    // store [s][o], packed hi/lo fp16 (8 contiguous o per thread)
#pragma unroll
    for (int i = 0; i < 4; i++) {
        int s = s0 + ts * 4 + i;
        size_t base = ((size_t)n * SQ + s) * CH + to * 8;
        __half2 qh[4], ql[4], kh[4], kl[4];
#pragma unroll
        for (int k2 = 0; k2 < 4; k2++) {
            cvt_hilo(qa[2 * k2][i], qa[2 * k2 + 1][i], qh[k2], ql[k2]);
            cvt_hilo(ka[2 * k2][i], ka[2 * k2 + 1][i], kh[k2], kl[k2]);
        }
        store4h2(&g_Qhi[base], qh[0], qh[1], qh[2], qh[3]);
        store4h2(&g_Qlo[base], ql[0], ql[1], ql[2], ql[3]);
        store4h2(&g_Khi[base], kh[0], kh[1], kh[2], kh[3]);
        store4h2(&g_Klo[base], kl[0], kl[1], kl[2], kl[3]);
    }
}

// ---------------------------------------------------------------------------
// Kernel 2: tensor-core flash attention, fp16 split precision (3-term MMA).
// BM=64, BN=64, d=128, dv=256. 8 warps: warp w -> m-tile (w&3), n-half (w>>2).
// SMEM offsets below are in __half units.
// ---------------------------------------------------------------------------
#define OQH 0
#define OQL 8704          // + 64*136
#define OKH 17408
#define OKL 26112
#define OVH 34816         // V [256 c][72]
#define OVL 53248
#define OPH 71680         // P [64][72]
#define OPL 76288
#define SM_HALFS 80896
#define RED_BYTES (SM_HALFS * 2)
#define FLASH_SMEM (RED_BYTES + 1024)

__global__ __launch_bounds__(256, 1) void flash_tc(const float* __restrict__ x,
                                                   float* __restrict__ out)
{
    extern __shared__ __half smh[];
    float* smax = (float*)((char*)smh + RED_BYTES);   // [2][64]
    float* ssum = smax + 128;                         // [2][64]
    const unsigned sb = (unsigned)__cvta_generic_to_shared(smh);

    const int n  = blockIdx.y;
    const int s0 = blockIdx.x * 64;
    const int tid = threadIdx.x;
    const int w  = tid >> 5;
    const int ln = tid & 31;
    const int wm = w & 3;
    const int wn = w >> 2;
    const int m0 = wm * 16;
    const int r0 = m0 + (ln >> 2);
    const int r1 = r0 + 8;

    // ---- load Q tile [64 s][128 d] hi/lo ----
    {
        int r = tid >> 2;
        int seg = tid & 3;
        size_t src = ((size_t)n * SQ + s0 + r) * CH + seg * 32;
        int dst = r * 136 + seg * 32;
#pragma unroll
        for (int j = 0; j < 4; j++) {
            *(uint4*)&smh[OQH + dst + j * 8] = *(const uint4*)&g_Qhi[src + j * 8];
            *(uint4*)&smh[OQL + dst + j * 8] = *(const uint4*)&g_Qlo[src + j * 8];
        }
    }

    float oacc[16][4];
#pragma unroll
    for (int t = 0; t < 16; t++) {
#pragma unroll
        for (int i = 0; i < 4; i++) oacc[t][i] = 0.f;
    }

    float mrow0 = -1e30f, mrow1 = -1e30f;
    float lrow0 = 0.f, lrow1 = 0.f;

    // ldmatrix base addresses (bytes)
    const unsigned a_q  = sb + 2u * (OQH + (m0 + (ln & 15)) * 136 + (ln >> 4) * 8);
    const unsigned a_ql = a_q + 2u * (OQL - OQH);
    const unsigned b_k  = sb + 2u * (OKH + (wn * 32 + (ln & 7)) * 136 + ((ln >> 3) & 1) * 8);
    const unsigned b_kl = b_k + 2u * (OKL - OKH);
    const unsigned a_p  = sb + 2u * (OPH + (m0 + (ln & 15)) * 72 + (ln >> 4) * 8);
    const unsigned a_pl = a_p + 2u * (OPL - OPH);
    const unsigned b_v  = sb + 2u * (OVH + (wn * 128 + (ln & 7)) * 72 + ((ln >> 3) & 1) * 8);
    const unsigned b_vl = b_v + 2u * (OVL - OVH);

    for (int t0 = 0; t0 < SQ; t0 += 64) {
        __syncthreads();   // S0: prev tile reads done

        // ---- K tile [64 t][128 d] hi/lo ----
        {
            int r = tid >> 2;
            int seg = tid & 3;
            size_t src = ((size_t)n * SQ + t0 + r) * CH + seg * 32;
            int dst = r * 136 + seg * 32;
#pragma unroll
            for (int j = 0; j < 4; j++) {
                *(uint4*)&smh[OKH + dst + j * 8] = *(const uint4*)&g_Khi[src + j * 8];
                *(uint4*)&smh[OKL + dst + j * 8] = *(const uint4*)&g_Klo[src + j * 8];
            }
        }
        // ---- V tile [256 c][64 t] hi/lo, converted from x ----
        {
            int si = (tid & 3) * 16;
            int cb = tid >> 2;
#pragma unroll
            for (int cc = 0; cc < 4; cc++) {
                int c = cb + cc * 64;
                const float4* xp = (const float4*)&x[((size_t)n * CIN + c) * SQ + t0 + si];
                __half2 th[8], tl[8];
#pragma unroll
                for (int j = 0; j < 4; j++) {
                    float4 f = xp[j];
                    cvt_hilo(f.x, f.y, th[2 * j], tl[2 * j]);
                    cvt_hilo(f.z, f.w, th[2 * j + 1], tl[2 * j + 1]);
                }
                int vd = c * 72 + si;
                store4h2(&smh[OVH + vd],     th[0], th[1], th[2], th[3]);
                store4h2(&smh[OVH + vd + 8], th[4], th[5], th[6], th[7]);
                store4h2(&smh[OVL + vd],     tl[0], tl[1], tl[2], tl[3]);
                store4h2(&smh[OVL + vd + 8], tl[4], tl[5], tl[6], tl[7]);
            }
        }
        __syncthreads();   // S1: operands ready

        // ---- S = Q K^T (3-term split), warp: m16 x n32 x k128 ----
        float sacc[4][4];
#pragma unroll
        for (int t = 0; t < 4; t++) {
#pragma unroll
            for (int i = 0; i < 4; i++) sacc[t][i] = 0.f;
        }

#pragma unroll
        for (int k = 0; k < 8; k++) {
            unsigned qh[4], ql4[4];
            ldsm_x4(qh,  a_q  + k * 32);
            ldsm_x4(ql4, a_ql + k * 32);
#pragma unroll
            for (int nt = 0; nt < 4; nt++) {
                unsigned kh[2], kl2[2];
                ldsm_x2(kh,  b_k  + nt * 2176 + k * 32);
                ldsm_x2(kl2, b_kl + nt * 2176 + k * 32);
                mma16816(sacc[nt], qh,  kh);
                mma16816(sacc[nt], qh,  kl2);
                mma16816(sacc[nt], ql4, kh);
            }
        }

        // ---- online softmax, cross-warp reduce via SMEM ----
        float rm0 = fmaxf(fmaxf(sacc[0][0], sacc[0][1]), fmaxf(sacc[1][0], sacc[1][1]));
        float rm1 = fmaxf(fmaxf(sacc[0][2], sacc[0][3]), fmaxf(sacc[1][2], sacc[1][3]));
        rm0 = fmaxf(rm0, fmaxf(fmaxf(sacc[2][0], sacc[2][1]), fmaxf(sacc[3][0], sacc[3][1])));
        rm1 = fmaxf(rm1, fmaxf(fmaxf(sacc[2][2], sacc[2][3]), fmaxf(sacc[3][2], sacc[3][3])));
        rm0 = fmaxf(rm0, __shfl_xor_sync(0xffffffffu, rm0, 1));
        rm0 = fmaxf(rm0, __shfl_xor_sync(0xffffffffu, rm0, 2));
        rm1 = fmaxf(rm1, __shfl_xor_sync(0xffffffffu, rm1, 1));
        rm1 = fmaxf(rm1, __shfl_xor_sync(0xffffffffu, rm1, 2));
        if ((ln & 3) == 0) {
            smax[wn * 64 + r0] = rm0;
            smax[wn * 64 + r1] = rm1;
        }
        __syncthreads();   // S2
        const float mn0 = fmaxf(mrow0, fmaxf(smax[r0], smax[64 + r0]));
        const float mn1 = fmaxf(mrow1, fmaxf(smax[r1], smax[64 + r1]));
        const float al0 = __expf(mrow0 - mn0);
        const float al1 = __expf(mrow1 - mn1);
        mrow0 = mn0;
        mrow1 = mn1;

        float sum0 = 0.f, sum1 = 0.f;
#pragma unroll
        for (int nt = 0; nt < 4; nt++) {
            float p0 = __expf(sacc[nt][0] - mn0);
            float p1 = __expf(sacc[nt][1] - mn0);
            float p2 = __expf(sacc[nt][2] - mn1);
            float p3 = __expf(sacc[nt][3] - mn1);
            sum0 += p0 + p1;
            sum1 += p2 + p3;
            int col = wn * 32 + nt * 8 + 2 * (ln & 3);
            __half h0 = __float2half_rn(p0);
            __half h1 = __float2half_rn(p1);
            __half h2 = __float2half_rn(p2);
            __half h3 = __float2half_rn(p3);
            *(__half2*)&smh[OPH + r0 * 72 + col] = __halves2half2(h0, h1);
            *(__half2*)&smh[OPH + r1 * 72 + col] = __halves2half2(h2, h3);
            *(__half2*)&smh[OPL + r0 * 72 + col] =
                __halves2half2(__float2half_rn(p0 - __half2float(h0)),
                               __float2half_rn(p1 - __half2float(h1)));
            *(__half2*)&smh[OPL + r1 * 72 + col] =
                __halves2half2(__float2half_rn(p2 - __half2float(h2)),
                               __float2half_rn(p3 - __half2float(h3)));
        }
        sum0 += __shfl_xor_sync(0xffffffffu, sum0, 1);
        sum0 += __shfl_xor_sync(0xffffffffu, sum0, 2);
        sum1 += __shfl_xor_sync(0xffffffffu, sum1, 1);
        sum1 += __shfl_xor_sync(0xffffffffu, sum1, 2);
        if ((ln & 3) == 0) {
            ssum[wn * 64 + r0] = sum0;
            ssum[wn * 64 + r1] = sum1;
        }

        // rescale O while sums land
#pragma unroll
        for (int nt = 0; nt < 16; nt++) {
            oacc[nt][0] *= al0;
            oacc[nt][1] *= al0;
            oacc[nt][2] *= al1;
            oacc[nt][3] *= al1;
        }
        __syncthreads();   // S3: P + sums visible
        lrow0 = lrow0 * al0 + ssum[r0] + ssum[64 + r0];
        lrow1 = lrow1 * al1 + ssum[r1] + ssum[64 + r1];

        // ---- O += P V (3-term split), warp: m16 x n128 x k64 ----
#pragma unroll
        for (int k = 0; k < 4; k++) {
            unsigned ph4[4], pl4[4];
            ldsm_x4(ph4, a_p  + k * 32);
            ldsm_x4(pl4, a_pl + k * 32);
#pragma unroll
            for (int nt = 0; nt < 16; nt++) {
                unsigned vh[2], vl2[2];
                ldsm_x2(vh,  b_v  + nt * 1152 + k * 32);
                ldsm_x2(vl2, b_vl + nt * 1152 + k * 32);
                mma16816(oacc[nt], ph4, vh);
                mma16816(oacc[nt], ph4, vl2);
                mma16816(oacc[nt], pl4, vh);
            }
        }
    }

    // ---- epilogue: normalize, two-pass SMEM transpose, residual add ----
    const float inv0 = 1.0f / lrow0;
    const float inv1 = 1.0f / lrow1;
#pragma unroll
    for (int nt = 0; nt < 16; nt++) {
        oacc[nt][0] *= inv0;
        oacc[nt][1] *= inv0;
        oacc[nt][2] *= inv1;
        oacc[nt][3] *= inv1;
    }

    float* stg = (float*)smh;   // [64][132] fp32 = 135168 B, fits in smem
    const int cl0 = tid & 127;
    const int sbase = (tid >> 7) * 32;
    for (int pass = 0; pass < 2; pass++) {
        __syncthreads();       // protect smem reuse / prev pass reads
        if (wn == pass) {
#pragma unroll
            for (int nt = 0; nt < 16; nt++) {
                int cl = nt * 8 + 2 * (ln & 3);
                *(float2*)&stg[r0 * 132 + cl] = make_float2(oacc[nt][0], oacc[nt][1]);
                *(float2*)&stg[r1 * 132 + cl] = make_float2(oacc[nt][2], oacc[nt][3]);
            }
        }
        __syncthreads();
        int c = pass * 128 + cl0;
        const float* xb = x   + ((size_t)n * CIN + c) * SQ + s0 + sbase;
        float*       ob = out + ((size_t)n * CIN + c) * SQ + s0 + sbase;
#pragma unroll
        for (int ss = 0; ss < 32; ss += 4) {
            float4 xv = *(const float4*)&xb[ss];
            float4 r;
            r.x = xv.x + stg[(sbase + ss + 0) * 132 + cl0];
            r.y = xv.y + stg[(sbase + ss + 1) * 132 + cl0];
            r.z = xv.z + stg[(sbase + ss + 2) * 132 + cl0];
            r.w = xv.w + stg[(sbase + ss + 3) * 132 + cl0];
            *(float4*)&ob[ss] = r;
        }
    }
}

// ---------------------------------------------------------------------------
extern "C" void kernel_launch(void* const* d_in, const int* in_sizes, int n_in,
                              void* d_out, int out_size)
{
    const float* x  = (const float*)d_in[0];   // [8,256,64,64]
    const float* tw = (const float*)d_in[1];   // [128,256]
    const float* pw = (const float*)d_in[2];   // [128,256]
    float* out = (float*)d_out;

    cudaFuncSetAttribute(flash_tc,
                         cudaFuncAttributeMaxDynamicSharedMemorySize, FLASH_SMEM);

    proj_kernel<<<dim3(64, 8), 256>>>(x, tw, pw);
    flash_tc<<<dim3(64, 8), 256, FLASH_SMEM>>>(x, out);
}

// round 7
// speedup vs baseline: 3.0714x; 1.2562x over previous
#include <cuda_runtime.h>
#include <cuda_fp16.h>
#include <math.h>

#define SQ  4096   // H*W
#define CIN 256    // C
#define CH  128    // C/2
#define NB  8      // batch

// Scratch: Q,K projections as fp16 hi/lo pairs, layout [n][s][d] (ldmatrix-ready)
__device__ __half g_Qhi[(size_t)NB * SQ * CH];
__device__ __half g_Qlo[(size_t)NB * SQ * CH];
__device__ __half g_Khi[(size_t)NB * SQ * CH];
__device__ __half g_Klo[(size_t)NB * SQ * CH];

// ---------------------------------------------------------------------------
// helpers
// ---------------------------------------------------------------------------
union H2U { __half2 h; unsigned u; };

__device__ __forceinline__ unsigned h2u(__half2 v) {
    H2U c; c.h = v; return c.u;
}

__device__ __forceinline__ void cvt_hilo(float a, float b, __half2& hi, __half2& lo) {
    __half ha = __float2half_rn(a);
    __half hb = __float2half_rn(b);
    hi = __halves2half2(ha, hb);
    lo = __halves2half2(__float2half_rn(a - __half2float(ha)),
                        __float2half_rn(b - __half2float(hb)));
}

__device__ __forceinline__ void store4h2(__half* p, __half2 v0, __half2 v1,
                                         __half2 v2, __half2 v3) {
    uint4 u;
    u.x = h2u(v0); u.y = h2u(v1); u.z = h2u(v2); u.w = h2u(v3);
    *(uint4*)p = u;
}

__device__ __forceinline__ void ldsm_x4(unsigned* r, unsigned addr) {
    asm volatile("ldmatrix.sync.aligned.m8n8.x4.shared.b16 {%0,%1,%2,%3},[%4];\n"
                 : "=r"(r[0]), "=r"(r[1]), "=r"(r[2]), "=r"(r[3]) : "r"(addr));
}

__device__ __forceinline__ void mma16816(float* d, const unsigned* a, const unsigned* b) {
    asm volatile("mma.sync.aligned.m16n8k16.row.col.f32.f16.f16.f32 "
                 "{%0,%1,%2,%3},{%4,%5,%6,%7},{%8,%9},{%0,%1,%2,%3};\n"
                 : "+f"(d[0]), "+f"(d[1]), "+f"(d[2]), "+f"(d[3])
                 : "r"(a[0]), "r"(a[1]), "r"(a[2]), "r"(a[3]), "r"(b[0]), "r"(b[1]));
}

// ---------------------------------------------------------------------------
// Kernel 1: 1x1-conv projections -> fp16 hi/lo, layout [n][s][o].
// Grid (64 s-tiles, 8 batches), 256 threads.
// ---------------------------------------------------------------------------
__global__ __launch_bounds__(256) void proj_kernel(const float* __restrict__ x,
                                                   const float* __restrict__ tw,
                                                   const float* __restrict__ pw)
{
    const int n  = blockIdx.y;
    const int s0 = blockIdx.x * 64;
    const int tid = threadIdx.x;
    const int ts = tid & 15;
    const int to = tid >> 4;

    __shared__ float xs [32][68];
    __shared__ float wts[128][33];
    __shared__ float wps[128][33];

    float qa[8][4], ka[8][4];
#pragma unroll
    for (int k = 0; k < 8; k++) {
#pragma unroll
        for (int i = 0; i < 4; i++) { qa[k][i] = 0.f; ka[k][i] = 0.f; }
    }

    const float* xb = x + (size_t)n * CIN * SQ;

    for (int c0 = 0; c0 < CIN; c0 += 32) {
        __syncthreads();
#pragma unroll
        for (int k = 0; k < 8; k++) {
            int idx = tid + 256 * k;
            int cc = idx >> 6;
            int ss = idx & 63;
            xs[cc][ss] = xb[(size_t)(c0 + cc) * SQ + s0 + ss];
        }
#pragma unroll
        for (int k = 0; k < 16; k++) {
            int idx = tid + 256 * k;
            int o = idx >> 5;
            int cc = idx & 31;
            wts[o][cc] = tw[o * CIN + c0 + cc];
            wps[o][cc] = pw[o * CIN + c0 + cc];
        }
        __syncthreads();
#pragma unroll
        for (int cc = 0; cc < 32; cc++) {
            float4 xv = *(const float4*)&xs[cc][ts * 4];
            float xr[4];
            xr[0] = xv.x; xr[1] = xv.y; xr[2] = xv.z; xr[3] = xv.w;
#pragma unroll
            for (int k = 0; k < 8; k++) {
                float twv = wts[to * 8 + k][cc];
                float pwv = wps[to * 8 + k][cc];
#pragma unroll
                for (int i = 0; i < 4; i++) {
                    qa[k][i] = fmaf(twv, xr[i], qa[k][i]);
                    ka[k][i] = fmaf(pwv, xr[i], ka[k][i]);
                }
            }
        }
    }
#pragma unroll
    for (int i = 0; i < 4; i++) {
        int s = s0 + ts * 4 + i;
        size_t base = ((size_t)n * SQ + s) * CH + to * 8;
        __half2 qh[4], ql[4], kh[4], kl[4];
#pragma unroll
        for (int k2 = 0; k2 < 4; k2++) {
            cvt_hilo(qa[2 * k2][i], qa[2 * k2 + 1][i], qh[k2], ql[k2]);
            cvt_hilo(ka[2 * k2][i], ka[2 * k2 + 1][i], kh[k2], kl[k2]);
        }
        store4h2(&g_Qhi[base], qh[0], qh[1], qh[2], qh[3]);
        store4h2(&g_Qlo[base], ql[0], ql[1], ql[2], ql[3]);
        store4h2(&g_Khi[base], kh[0], kh[1], kh[2], kh[3]);
        store4h2(&g_Klo[base], kl[0], kl[1], kl[2], kl[3]);
    }
}

// ---------------------------------------------------------------------------
// Kernel 2: tensor-core flash attention, fp16 split precision (3-term MMA).
// BM=128, BN=64, d=128, dv=256. 16 warps: wm = w&7 (m-tile), wn = w>>3 (n-half).
// SMEM offsets below are in __half units.
// ---------------------------------------------------------------------------
#define OQH 0
#define OQL 17408         // + 128*136
#define OKH 34816
#define OKL 43520         // + 64*136
#define OVH 52224         // V [256 c][72]
#define OVL 70656
#define OPH 89088         // P [128][72]
#define OPL 98304
#define SM_HALFS 107520
#define RED_BYTES (SM_HALFS * 2)
#define FLASH_SMEM (RED_BYTES + 2048)

__global__ __launch_bounds__(512, 1) void flash_tc(const float* __restrict__ x,
                                                   float* __restrict__ out)
{
    extern __shared__ __half smh[];
    float* smax = (float*)((char*)smh + RED_BYTES);   // [2][128]
    float* ssum = smax + 256;                         // [2][128]
    const unsigned sb = (unsigned)__cvta_generic_to_shared(smh);

    const int n  = blockIdx.y;
    const int s0 = blockIdx.x * 128;
    const int tid = threadIdx.x;
    const int w  = tid >> 5;
    const int ln = tid & 31;
    const int wm = w & 7;
    const int wn = w >> 3;
    const int m0 = wm * 16;
    const int r0 = m0 + (ln >> 2);
    const int r1 = r0 + 8;

    // ---- load Q tile [128 s][128 d] hi/lo ----
    {
        int r = tid >> 2;          // 0..127
        int seg = tid & 3;
        size_t src = ((size_t)n * SQ + s0 + r) * CH + seg * 32;
        int dst = r * 136 + seg * 32;
#pragma unroll
        for (int j = 0; j < 4; j++) {
            *(uint4*)&smh[OQH + dst + j * 8] = *(const uint4*)&g_Qhi[src + j * 8];
            *(uint4*)&smh[OQL + dst + j * 8] = *(const uint4*)&g_Qlo[src + j * 8];
        }
    }

    float oacc[16][4];
#pragma unroll
    for (int t = 0; t < 16; t++) {
#pragma unroll
        for (int i = 0; i < 4; i++) oacc[t][i] = 0.f;
    }

    float mrow0 = -1e30f, mrow1 = -1e30f;
    float lrow0 = 0.f, lrow1 = 0.f;

    // ldmatrix base addresses (bytes)
    const unsigned a_q  = sb + 2u * (OQH + (m0 + (ln & 15)) * 136 + (ln >> 4) * 8);
    const unsigned a_ql = a_q + 2u * (OQL - OQH);
    const unsigned b_k  = sb + 2u * (OKH + (wn * 32 + (ln & 7) + ((ln >> 4) & 1) * 8) * 136
                                         + ((ln >> 3) & 1) * 8);
    const unsigned b_kl = b_k + 2u * (OKL - OKH);
    const unsigned a_p  = sb + 2u * (OPH + (m0 + (ln & 15)) * 72 + (ln >> 4) * 8);
    const unsigned a_pl = a_p + 2u * (OPL - OPH);
    const unsigned b_v  = sb + 2u * (OVH + (wn * 128 + (ln & 7) + ((ln >> 4) & 1) * 8) * 72
                                         + ((ln >> 3) & 1) * 8);
    const unsigned b_vl = b_v + 2u * (OVL - OVH);

    for (int t0 = 0; t0 < SQ; t0 += 64) {
        __syncthreads();   // S0: prev tile reads done

        // ---- K tile [64 t][128 d] hi/lo ----
        {
            int r = tid >> 3;          // 0..63
            int seg = tid & 7;
            size_t src = ((size_t)n * SQ + t0 + r) * CH + seg * 16;
            int dst = r * 136 + seg * 16;
#pragma unroll
            for (int j = 0; j < 2; j++) {
                *(uint4*)&smh[OKH + dst + j * 8] = *(const uint4*)&g_Khi[src + j * 8];
                *(uint4*)&smh[OKL + dst + j * 8] = *(const uint4*)&g_Klo[src + j * 8];
            }
        }
        // ---- V tile [256 c][64 t] hi/lo, converted from x ----
        {
            int si = (tid & 3) * 16;
            int cb = tid >> 2;        // 0..127
#pragma unroll
            for (int cc = 0; cc < 2; cc++) {
                int c = cb + cc * 128;
                const float4* xp = (const float4*)&x[((size_t)n * CIN + c) * SQ + t0 + si];
                __half2 th[8], tl[8];
#pragma unroll
                for (int j = 0; j < 4; j++) {
                    float4 f = xp[j];
                    cvt_hilo(f.x, f.y, th[2 * j], tl[2 * j]);
                    cvt_hilo(f.z, f.w, th[2 * j + 1], tl[2 * j + 1]);
                }
                int vd = c * 72 + si;
                store4h2(&smh[OVH + vd],     th[0], th[1], th[2], th[3]);
                store4h2(&smh[OVH + vd + 8], th[4], th[5], th[6], th[7]);
                store4h2(&smh[OVL + vd],     tl[0], tl[1], tl[2], tl[3]);
                store4h2(&smh[OVL + vd + 8], tl[4], tl[5], tl[6], tl[7]);
            }
        }
        __syncthreads();   // S1: operands ready

        // ---- S = Q K^T (3-term split), warp: m16 x n32 x k128 ----
        float sacc[4][4];
#pragma unroll
        for (int t = 0; t < 4; t++) {
#pragma unroll
            for (int i = 0; i < 4; i++) sacc[t][i] = 0.f;
        }

#pragma unroll
        for (int k = 0; k < 8; k++) {
            unsigned qh[4], ql4[4];
            ldsm_x4(qh,  a_q  + k * 32);
            ldsm_x4(ql4, a_ql + k * 32);
#pragma unroll
            for (int ntp = 0; ntp < 2; ntp++) {
                unsigned kh4[4], kl4[4];
                ldsm_x4(kh4, b_k  + ntp * 4352 + k * 32);
                ldsm_x4(kl4, b_kl + ntp * 4352 + k * 32);
                mma16816(sacc[2 * ntp],     qh,  kh4);
                mma16816(sacc[2 * ntp],     qh,  kl4);
                mma16816(sacc[2 * ntp],     ql4, kh4);
                mma16816(sacc[2 * ntp + 1], qh,  kh4 + 2);
                mma16816(sacc[2 * ntp + 1], qh,  kl4 + 2);
                mma16816(sacc[2 * ntp + 1], ql4, kh4 + 2);
            }
        }

        // ---- online softmax, cross-warp (wn) reduce via SMEM ----
        float rm0 = fmaxf(fmaxf(sacc[0][0], sacc[0][1]), fmaxf(sacc[1][0], sacc[1][1]));
        float rm1 = fmaxf(fmaxf(sacc[0][2], sacc[0][3]), fmaxf(sacc[1][2], sacc[1][3]));
        rm0 = fmaxf(rm0, fmaxf(fmaxf(sacc[2][0], sacc[2][1]), fmaxf(sacc[3][0], sacc[3][1])));
        rm1 = fmaxf(rm1, fmaxf(fmaxf(sacc[2][2], sacc[2][3]), fmaxf(sacc[3][2], sacc[3][3])));
        rm0 = fmaxf(rm0, __shfl_xor_sync(0xffffffffu, rm0, 1));
        rm0 = fmaxf(rm0, __shfl_xor_sync(0xffffffffu, rm0, 2));
        rm1 = fmaxf(rm1, __shfl_xor_sync(0xffffffffu, rm1, 1));
        rm1 = fmaxf(rm1, __shfl_xor_sync(0xffffffffu, rm1, 2));
        if ((ln & 3) == 0) {
            smax[wn * 128 + r0] = rm0;
            smax[wn * 128 + r1] = rm1;
        }
        __syncthreads();   // S2
        const float mn0 = fmaxf(mrow0, fmaxf(smax[r0], smax[128 + r0]));
        const float mn1 = fmaxf(mrow1, fmaxf(smax[r1], smax[128 + r1]));
        const float al0 = __expf(mrow0 - mn0);
        const float al1 = __expf(mrow1 - mn1);
        mrow0 = mn0;
        mrow1 = mn1;

        float sum0 = 0.f, sum1 = 0.f;
#pragma unroll
        for (int nt = 0; nt < 4; nt++) {
            float p0 = __expf(sacc[nt][0] - mn0);
            float p1 = __expf(sacc[nt][1] - mn0);
            float p2 = __expf(sacc[nt][2] - mn1);
            float p3 = __expf(sacc[nt][3] - mn1);
            sum0 += p0 + p1;
            sum1 += p2 + p3;
            int col = wn * 32 + nt * 8 + 2 * (ln & 3);
            __half h0 = __float2half_rn(p0);
            __half h1 = __float2half_rn(p1);
            __half h2 = __float2half_rn(p2);
            __half h3 = __float2half_rn(p3);
            *(__half2*)&smh[OPH + r0 * 72 + col] = __halves2half2(h0, h1);
            *(__half2*)&smh[OPH + r1 * 72 + col] = __halves2half2(h2, h3);
            *(__half2*)&smh[OPL + r0 * 72 + col] =
                __halves2half2(__float2half_rn(p0 - __half2float(h0)),
                               __float2half_rn(p1 - __half2float(h1)));
            *(__half2*)&smh[OPL + r1 * 72 + col] =
                __halves2half2(__float2half_rn(p2 - __half2float(h2)),
                               __float2half_rn(p3 - __half2float(h3)));
        }
        sum0 += __shfl_xor_sync(0xffffffffu, sum0, 1);
        sum0 += __shfl_xor_sync(0xffffffffu, sum0, 2);
        sum1 += __shfl_xor_sync(0xffffffffu, sum1, 1);
        sum1 += __shfl_xor_sync(0xffffffffu, sum1, 2);
        if ((ln & 3) == 0) {
            ssum[wn * 128 + r0] = sum0;
            ssum[wn * 128 + r1] = sum1;
        }

        // rescale O while sums land
#pragma unroll
        for (int nt = 0; nt < 16; nt++) {
            oacc[nt][0] *= al0;
            oacc[nt][1] *= al0;
            oacc[nt][2] *= al1;
            oacc[nt][3] *= al1;
        }
        __syncthreads();   // S3: P + sums visible
        lrow0 = lrow0 * al0 + ssum[r0] + ssum[128 + r0];
        lrow1 = lrow1 * al1 + ssum[r1] + ssum[128 + r1];

        // ---- O += P V (3-term split), warp: m16 x n128 x k64 ----
#pragma unroll
        for (int k = 0; k < 4; k++) {
            unsigned ph4[4], pl4[4];
            ldsm_x4(ph4, a_p  + k * 32);
            ldsm_x4(pl4, a_pl + k * 32);
#pragma unroll
            for (int ntp = 0; ntp < 8; ntp++) {
                unsigned vh4[4], vl4[4];
                ldsm_x4(vh4, b_v  + ntp * 2304 + k * 32);
                ldsm_x4(vl4, b_vl + ntp * 2304 + k * 32);
                mma16816(oacc[2 * ntp],     ph4, vh4);
                mma16816(oacc[2 * ntp],     ph4, vl4);
                mma16816(oacc[2 * ntp],     pl4, vh4);
                mma16816(oacc[2 * ntp + 1], ph4, vh4 + 2);
                mma16816(oacc[2 * ntp + 1], ph4, vl4 + 2);
                mma16816(oacc[2 * ntp + 1], pl4, vh4 + 2);
            }
        }
    }

    // ---- epilogue: normalize, two-pass (channel-half) transpose, residual ----
    const float inv0 = 1.0f / lrow0;
    const float inv1 = 1.0f / lrow1;
#pragma unroll
    for (int nt = 0; nt < 16; nt++) {
        oacc[nt][0] *= inv0;
        oacc[nt][1] *= inv0;
        oacc[nt][2] *= inv1;
        oacc[nt][3] *= inv1;
    }

    float* stg = (float*)smh;   // [128][132] fp32 = 67584 B
    const int cl0 = tid & 127;
    const int sbase = (tid >> 7) * 32;
    for (int pass = 0; pass < 2; pass++) {
        __syncthreads();
        if (wn == pass) {
#pragma unroll
            for (int nt = 0; nt < 16; nt++) {
                int cl = nt * 8 + 2 * (ln & 3);
                *(float2*)&stg[r0 * 132 + cl] = make_float2(oacc[nt][0], oacc[nt][1]);
                *(float2*)&stg[r1 * 132 + cl] = make_float2(oacc[nt][2], oacc[nt][3]);
            }
        }
        __syncthreads();
        int c = pass * 128 + cl0;
        const float* xb = x   + ((size_t)n * CIN + c) * SQ + s0 + sbase;
        float*       ob = out + ((size_t)n * CIN + c) * SQ + s0 + sbase;
#pragma unroll
        for (int ss = 0; ss < 32; ss += 4) {
            float4 xv = *(const float4*)&xb[ss];
            float4 r;
            r.x = xv.x + stg[(sbase + ss + 0) * 132 + cl0];
            r.y = xv.y + stg[(sbase + ss + 1) * 132 + cl0];
            r.z = xv.z + stg[(sbase + ss + 2) * 132 + cl0];
            r.w = xv.w + stg[(sbase + ss + 3) * 132 + cl0];
            *(float4*)&ob[ss] = r;
        }
    }
}

// ---------------------------------------------------------------------------
extern "C" void kernel_launch(void* const* d_in, const int* in_sizes, int n_in,
                              void* d_out, int out_size)
{
    const float* x  = (const float*)d_in[0];   // [8,256,64,64]
    const float* tw = (const float*)d_in[1];   // [128,256]
    const float* pw = (const float*)d_in[2];   // [128,256]
    float* out = (float*)d_out;

    cudaFuncSetAttribute(flash_tc,
                         cudaFuncAttributeMaxDynamicSharedMemorySize, FLASH_SMEM);

    proj_kernel<<<dim3(64, 8), 256>>>(x, tw, pw);
    flash_tc<<<dim3(32, 8), 512, FLASH_SMEM>>>(x, out);
}

// round 8
// speedup vs baseline: 3.3602x; 1.0940x over previous
#include <cuda_runtime.h>
#include <cuda_fp16.h>
#include <math.h>

#define SQ  4096   // H*W
#define CIN 256    // C
#define CH  128    // C/2
#define NB  8      // batch

// Scratch: Q,K projections as fp16 hi/lo pairs, layout [n][s][d] (ldmatrix-ready)
__device__ __half g_Qhi[(size_t)NB * SQ * CH];
__device__ __half g_Qlo[(size_t)NB * SQ * CH];
__device__ __half g_Khi[(size_t)NB * SQ * CH];
__device__ __half g_Klo[(size_t)NB * SQ * CH];

// ---------------------------------------------------------------------------
// helpers
// ---------------------------------------------------------------------------
union H2U { __half2 h; unsigned u; };

__device__ __forceinline__ unsigned h2u(__half2 v) {
    H2U c; c.h = v; return c.u;
}

__device__ __forceinline__ void cvt_hilo(float a, float b, __half2& hi, __half2& lo) {
    __half ha = __float2half_rn(a);
    __half hb = __float2half_rn(b);
    hi = __halves2half2(ha, hb);
    lo = __halves2half2(__float2half_rn(a - __half2float(ha)),
                        __float2half_rn(b - __half2float(hb)));
}

__device__ __forceinline__ void store4h2(__half* p, __half2 v0, __half2 v1,
                                         __half2 v2, __half2 v3) {
    uint4 u;
    u.x = h2u(v0); u.y = h2u(v1); u.z = h2u(v2); u.w = h2u(v3);
    *(uint4*)p = u;
}

__device__ __forceinline__ void ldsm_x4(unsigned* r, unsigned addr) {
    asm volatile("ldmatrix.sync.aligned.m8n8.x4.shared.b16 {%0,%1,%2,%3},[%4];\n"
                 : "=r"(r[0]), "=r"(r[1]), "=r"(r[2]), "=r"(r[3]) : "r"(addr));
}

__device__ __forceinline__ void mma16816(float* d, const unsigned* a, const unsigned* b) {
    asm volatile("mma.sync.aligned.m16n8k16.row.col.f32.f16.f16.f32 "
                 "{%0,%1,%2,%3},{%4,%5,%6,%7},{%8,%9},{%0,%1,%2,%3};\n"
                 : "+f"(d[0]), "+f"(d[1]), "+f"(d[2]), "+f"(d[3])
                 : "r"(a[0]), "r"(a[1]), "r"(a[2]), "r"(a[3]), "r"(b[0]), "r"(b[1]));
}

// ---------------------------------------------------------------------------
// Kernel 1: 1x1-conv projections -> fp16 hi/lo, layout [n][s][o].
// Grid (64 s-tiles, 8 batches), 256 threads.
// ---------------------------------------------------------------------------
__global__ __launch_bounds__(256) void proj_kernel(const float* __restrict__ x,
                                                   const float* __restrict__ tw,
                                                   const float* __restrict__ pw)
{
    const int n  = blockIdx.y;
    const int s0 = blockIdx.x * 64;
    const int tid = threadIdx.x;
    const int ts = tid & 15;
    const int to = tid >> 4;

    __shared__ float xs [32][68];
    __shared__ float wts[128][33];
    __shared__ float wps[128][33];

    float qa[8][4], ka[8][4];
#pragma unroll
    for (int k = 0; k < 8; k++) {
#pragma unroll
        for (int i = 0; i < 4; i++) { qa[k][i] = 0.f; ka[k][i] = 0.f; }
    }

    const float* xb = x + (size_t)n * CIN * SQ;

    for (int c0 = 0; c0 < CIN; c0 += 32) {
        __syncthreads();
#pragma unroll
        for (int k = 0; k < 8; k++) {
            int idx = tid + 256 * k;
            int cc = idx >> 6;
            int ss = idx & 63;
            xs[cc][ss] = xb[(size_t)(c0 + cc) * SQ + s0 + ss];
        }
#pragma unroll
        for (int k = 0; k < 16; k++) {
            int idx = tid + 256 * k;
            int o = idx >> 5;
            int cc = idx & 31;
            wts[o][cc] = tw[o * CIN + c0 + cc];
            wps[o][cc] = pw[o * CIN + c0 + cc];
        }
        __syncthreads();
#pragma unroll
        for (int cc = 0; cc < 32; cc++) {
            float4 xv = *(const float4*)&xs[cc][ts * 4];
            float xr[4];
            xr[0] = xv.x; xr[1] = xv.y; xr[2] = xv.z; xr[3] = xv.w;
#pragma unroll
            for (int k = 0; k < 8; k++) {
                float twv = wts[to * 8 + k][cc];
                float pwv = wps[to * 8 + k][cc];
#pragma unroll
                for (int i = 0; i < 4; i++) {
                    qa[k][i] = fmaf(twv, xr[i], qa[k][i]);
                    ka[k][i] = fmaf(pwv, xr[i], ka[k][i]);
                }
            }
        }
    }
#pragma unroll
    for (int i = 0; i < 4; i++) {
        int s = s0 + ts * 4 + i;
        size_t base = ((size_t)n * SQ + s) * CH + to * 8;
        __half2 qh[4], ql[4], kh[4], kl[4];
#pragma unroll
        for (int k2 = 0; k2 < 4; k2++) {
            cvt_hilo(qa[2 * k2][i], qa[2 * k2 + 1][i], qh[k2], ql[k2]);
            cvt_hilo(ka[2 * k2][i], ka[2 * k2 + 1][i], kh[k2], kl[k2]);
        }
        store4h2(&g_Qhi[base], qh[0], qh[1], qh[2], qh[3]);
        store4h2(&g_Qlo[base], ql[0], ql[1], ql[2], ql[3]);
        store4h2(&g_Khi[base], kh[0], kh[1], kh[2], kh[3]);
        store4h2(&g_Klo[base], kl[0], kl[1], kl[2], kl[3]);
    }
}

// ---------------------------------------------------------------------------
// Kernel 2: flash attention, P kept in registers (FA-2 style).
// BM=128, BN=64, d=128, dv=256. 8 warps: warp w owns m16 rows, full n.
// QK: 3-term fp16 split. PV: 2-term (P hi/lo in regs, V plain fp16).
// SMEM offsets in __half units.
// ---------------------------------------------------------------------------
#define OQH 0
#define OQL 17408         // + 128*136
#define OKH 34816
#define OKL 43520         // + 64*136
#define OVH 52224         // V fp16 [256 c][72], XOR chunk swizzle
#define SM_HALFS 70656
#define FLASH_SMEM (SM_HALFS * 2)   // 141312 B

__global__ __launch_bounds__(256, 1) void flash_tc(const float* __restrict__ x,
                                                   float* __restrict__ out)
{
    extern __shared__ __half smh[];
    const unsigned sb = (unsigned)__cvta_generic_to_shared(smh);

    const int n  = blockIdx.y;
    const int s0 = blockIdx.x * 128;
    const int tid = threadIdx.x;
    const int w  = tid >> 5;
    const int ln = tid & 31;
    const int m0 = w * 16;
    const int q3 = ln & 3;
    const int rq = ln >> 2;            // quad row within m16

    // ---- load Q tile [128 s][128 d] hi/lo ----
    {
        int r = tid >> 1;              // 0..127
        int seg = tid & 1;             // 2 x 64 halves
        size_t src = ((size_t)n * SQ + s0 + r) * CH + seg * 64;
        int dst = r * 136 + seg * 64;
#pragma unroll
        for (int j = 0; j < 8; j++) {
            *(uint4*)&smh[OQH + dst + j * 8] = *(const uint4*)&g_Qhi[src + j * 8];
            *(uint4*)&smh[OQL + dst + j * 8] = *(const uint4*)&g_Qlo[src + j * 8];
        }
    }

    float oacc[32][4];
#pragma unroll
    for (int t = 0; t < 32; t++) {
#pragma unroll
        for (int i = 0; i < 4; i++) oacc[t][i] = 0.f;
    }

    float mrow0 = -1e30f, mrow1 = -1e30f;
    float lrow0 = 0.f, lrow1 = 0.f;

    // ldmatrix base addresses (bytes)
    const unsigned a_q  = sb + 2u * (OQH + (m0 + (ln & 15)) * 136 + (ln >> 4) * 8);
    const unsigned a_ql = a_q + 2u * (OQL - OQH);
    const unsigned b_k  = sb + 2u * (OKH + ((ln & 7) + ((ln >> 4) & 1) * 8) * 136
                                         + ((ln >> 3) & 1) * 8);
    const unsigned b_kl = b_k + 2u * (OKL - OKH);
    const int bb = (ln >> 4) & 1;                         // row+8 selector
    const int vrow_in = (ln & 7) + bb * 8;
    const unsigned v_base = sb + 2u * OVH + ((ln >> 3) & 1) * 16;

    for (int t0 = 0; t0 < SQ; t0 += 64) {
        __syncthreads();   // S0: prev tile K/V reads done

        // ---- K tile [64 t][128 d] hi/lo ----
        {
            int r = tid >> 2;          // 0..63
            int seg = tid & 3;         // 4 x 32 halves
            size_t src = ((size_t)n * SQ + t0 + r) * CH + seg * 32;
            int dst = r * 136 + seg * 32;
#pragma unroll
            for (int j = 0; j < 4; j++) {
                *(uint4*)&smh[OKH + dst + j * 8] = *(const uint4*)&g_Khi[src + j * 8];
                *(uint4*)&smh[OKL + dst + j * 8] = *(const uint4*)&g_Klo[src + j * 8];
            }
        }
        // ---- V tile [256 c][64 t] fp16, XOR chunk swizzle ----
        {
            int c = tid;
            const float4* xp = (const float4*)&x[((size_t)n * CIN + c) * SQ + t0];
            __half2 th[32];
#pragma unroll
            for (int j = 0; j < 16; j++) {
                float4 f = xp[j];
                th[2 * j]     = __floats2half2_rn(f.x, f.y);
                th[2 * j + 1] = __floats2half2_rn(f.z, f.w);
            }
            int sw = (c & 3) ^ ((c >> 3) & 3);
#pragma unroll
            for (int ch = 0; ch < 4; ch++) {
                int pos = ch ^ sw;
                __half* dst = &smh[OVH + c * 72 + pos * 16];
                store4h2(dst,     th[ch * 8 + 0], th[ch * 8 + 1],
                                  th[ch * 8 + 2], th[ch * 8 + 3]);
                store4h2(dst + 8, th[ch * 8 + 4], th[ch * 8 + 5],
                                  th[ch * 8 + 6], th[ch * 8 + 7]);
            }
        }
        __syncthreads();   // S1: operands ready

        // ---- S = Q K^T (3-term split), warp: m16 x n64 x k128 ----
        float sacc[8][4];
#pragma unroll
        for (int t = 0; t < 8; t++) {
#pragma unroll
            for (int i = 0; i < 4; i++) sacc[t][i] = 0.f;
        }

#pragma unroll
        for (int k = 0; k < 8; k++) {
            unsigned qh[4], ql4[4];
            ldsm_x4(qh,  a_q  + k * 32);
            ldsm_x4(ql4, a_ql + k * 32);
#pragma unroll
            for (int nb = 0; nb < 4; nb++) {
                unsigned kh4[4], kl4[4];
                ldsm_x4(kh4, b_k  + nb * 4352 + k * 32);
                ldsm_x4(kl4, b_kl + nb * 4352 + k * 32);
                mma16816(sacc[2 * nb],     qh,  kh4);
                mma16816(sacc[2 * nb],     qh,  kl4);
                mma16816(sacc[2 * nb],     ql4, kh4);
                mma16816(sacc[2 * nb + 1], qh,  kh4 + 2);
                mma16816(sacc[2 * nb + 1], qh,  kl4 + 2);
                mma16816(sacc[2 * nb + 1], ql4, kh4 + 2);
            }
        }

        // ---- softmax: full row per warp, quad-shuffle reduce only ----
        float rm0 = -1e30f, rm1 = -1e30f;
#pragma unroll
        for (int nt = 0; nt < 8; nt++) {
            rm0 = fmaxf(rm0, fmaxf(sacc[nt][0], sacc[nt][1]));
            rm1 = fmaxf(rm1, fmaxf(sacc[nt][2], sacc[nt][3]));
        }
        rm0 = fmaxf(rm0, __shfl_xor_sync(0xffffffffu, rm0, 1));
        rm0 = fmaxf(rm0, __shfl_xor_sync(0xffffffffu, rm0, 2));
        rm1 = fmaxf(rm1, __shfl_xor_sync(0xffffffffu, rm1, 1));
        rm1 = fmaxf(rm1, __shfl_xor_sync(0xffffffffu, rm1, 2));
        const float mn0 = fmaxf(mrow0, rm0);
        const float mn1 = fmaxf(mrow1, rm1);
        const float al0 = __expf(mrow0 - mn0);
        const float al1 = __expf(mrow1 - mn1);
        mrow0 = mn0;
        mrow1 = mn1;

        float sum0 = 0.f, sum1 = 0.f;
#pragma unroll
        for (int nt = 0; nt < 8; nt++) {
            sacc[nt][0] = __expf(sacc[nt][0] - mn0);
            sacc[nt][1] = __expf(sacc[nt][1] - mn0);
            sacc[nt][2] = __expf(sacc[nt][2] - mn1);
            sacc[nt][3] = __expf(sacc[nt][3] - mn1);
            sum0 += sacc[nt][0] + sacc[nt][1];
            sum1 += sacc[nt][2] + sacc[nt][3];
        }
        sum0 += __shfl_xor_sync(0xffffffffu, sum0, 1);
        sum0 += __shfl_xor_sync(0xffffffffu, sum0, 2);
        sum1 += __shfl_xor_sync(0xffffffffu, sum1, 1);
        sum1 += __shfl_xor_sync(0xffffffffu, sum1, 2);
        lrow0 = lrow0 * al0 + sum0;
        lrow1 = lrow1 * al1 + sum1;

        // rescale O
#pragma unroll
        for (int nt = 0; nt < 32; nt++) {
            oacc[nt][0] *= al0;
            oacc[nt][1] *= al0;
            oacc[nt][2] *= al1;
            oacc[nt][3] *= al1;
        }

        // ---- O += P V : P hi/lo packed from registers, V fp16 in SMEM ----
#pragma unroll
        for (int kc = 0; kc < 4; kc++) {
            // A fragment (m16 k16) from C-fragment identity
            unsigned ah[4], alo[4];
            {
                __half2 h0 = __floats2half2_rn(sacc[2 * kc][0],     sacc[2 * kc][1]);
                __half2 h1 = __floats2half2_rn(sacc[2 * kc][2],     sacc[2 * kc][3]);
                __half2 h2 = __floats2half2_rn(sacc[2 * kc + 1][0], sacc[2 * kc + 1][1]);
                __half2 h3 = __floats2half2_rn(sacc[2 * kc + 1][2], sacc[2 * kc + 1][3]);
                float2 f0 = __half22float2(h0);
                float2 f1 = __half22float2(h1);
                float2 f2 = __half22float2(h2);
                float2 f3 = __half22float2(h3);
                ah[0] = h2u(h0); ah[1] = h2u(h1); ah[2] = h2u(h2); ah[3] = h2u(h3);
                alo[0] = h2u(__floats2half2_rn(sacc[2 * kc][0] - f0.x,
                                               sacc[2 * kc][1] - f0.y));
                alo[1] = h2u(__floats2half2_rn(sacc[2 * kc][2] - f1.x,
                                               sacc[2 * kc][3] - f1.y));
                alo[2] = h2u(__floats2half2_rn(sacc[2 * kc + 1][0] - f2.x,
                                               sacc[2 * kc + 1][1] - f2.y));
                alo[3] = h2u(__floats2half2_rn(sacc[2 * kc + 1][2] - f3.x,
                                               sacc[2 * kc + 1][3] - f3.y));
            }
#pragma unroll
            for (int nb = 0; nb < 16; nb++) {
                int crow = nb * 16 + vrow_in;
                unsigned vaddr = v_base + crow * 144
                               + (((kc ^ q3 ^ ((2 * nb + bb) & 3)) & 3) << 5);
                unsigned vh4[4];
                ldsm_x4(vh4, vaddr);
                mma16816(oacc[2 * nb],     ah,  vh4);
                mma16816(oacc[2 * nb],     alo, vh4);
                mma16816(oacc[2 * nb + 1], ah,  vh4 + 2);
                mma16816(oacc[2 * nb + 1], alo, vh4 + 2);
            }
        }
    }

    // ---- epilogue: normalize, two-pass SMEM transpose, residual add ----
    const float inv0 = 1.0f / lrow0;
    const float inv1 = 1.0f / lrow1;
#pragma unroll
    for (int nt = 0; nt < 32; nt++) {
        oacc[nt][0] *= inv0;
        oacc[nt][1] *= inv0;
        oacc[nt][2] *= inv1;
        oacc[nt][3] *= inv1;
    }

    float* stg = (float*)smh;   // [128 s][132] fp32 = 67584 B, overlays tiles
    const int cl0 = tid & 127;
    const int sg  = tid >> 7;   // 0,1 : s-half
    for (int pass = 0; pass < 2; pass++) {
        __syncthreads();
#pragma unroll
        for (int nt2 = 0; nt2 < 16; nt2++) {
            int nt = pass * 16 + nt2;
            int cl = nt2 * 8 + 2 * q3;
            *(float2*)&stg[(m0 + rq) * 132 + cl] =
                make_float2(oacc[nt][0], oacc[nt][1]);
            *(float2*)&stg[(m0 + rq + 8) * 132 + cl] =
                make_float2(oacc[nt][2], oacc[nt][3]);
        }
        __syncthreads();
        int c = pass * 128 + cl0;
        const float* xb = x   + ((size_t)n * CIN + c) * SQ + s0 + sg * 64;
        float*       ob = out + ((size_t)n * CIN + c) * SQ + s0 + sg * 64;
#pragma unroll
        for (int ss = 0; ss < 64; ss += 4) {
            float4 xv = *(const float4*)&xb[ss];
            float4 r;
            r.x = xv.x + stg[(sg * 64 + ss + 0) * 132 + cl0];
            r.y = xv.y + stg[(sg * 64 + ss + 1) * 132 + cl0];
            r.z = xv.z + stg[(sg * 64 + ss + 2) * 132 + cl0];
            r.w = xv.w + stg[(sg * 64 + ss + 3) * 132 + cl0];
            *(float4*)&ob[ss] = r;
        }
    }
}

// ---------------------------------------------------------------------------
extern "C" void kernel_launch(void* const* d_in, const int* in_sizes, int n_in,
                              void* d_out, int out_size)
{
    const float* x  = (const float*)d_in[0];   // [8,256,64,64]
    const float* tw = (const float*)d_in[1];   // [128,256]
    const float* pw = (const float*)d_in[2];   // [128,256]
    float* out = (float*)d_out;

    cudaFuncSetAttribute(flash_tc,
                         cudaFuncAttributeMaxDynamicSharedMemorySize, FLASH_SMEM);

    proj_kernel<<<dim3(64, 8), 256>>>(x, tw, pw);
    flash_tc<<<dim3(32, 8), 256, FLASH_SMEM>>>(x, out);
}

// round 11
// speedup vs baseline: 5.1674x; 1.5378x over previous
#include <cuda_runtime.h>
#include <cuda_fp16.h>
#include <math.h>

#define SQ  4096   // H*W
#define CIN 256    // C
#define CH  128    // C/2
#define NB  8      // batch

// Scratch: Q,K fp16 hi/lo [n][s][d] rows pre-swizzled; V fp16 [n][c][s] granule-swizzled
__device__ __half g_Qhi[(size_t)NB * SQ * CH];
__device__ __half g_Qlo[(size_t)NB * SQ * CH];
__device__ __half g_Khi[(size_t)NB * SQ * CH];
__device__ __half g_Klo[(size_t)NB * SQ * CH];
__device__ __half g_V  [(size_t)NB * CIN * SQ];

// ---------------------------------------------------------------------------
// helpers
// ---------------------------------------------------------------------------
union H2U { __half2 h; unsigned u; };

__device__ __forceinline__ unsigned h2u(__half2 v) { H2U c; c.h = v; return c.u; }

__device__ __forceinline__ void cvt_hilo(float a, float b, __half2& hi, __half2& lo) {
    __half ha = __float2half_rn(a);
    __half hb = __float2half_rn(b);
    hi = __halves2half2(ha, hb);
    lo = __halves2half2(__float2half_rn(a - __half2float(ha)),
                        __float2half_rn(b - __half2float(hb)));
}

__device__ __forceinline__ void store4h2(__half* p, __half2 v0, __half2 v1,
                                         __half2 v2, __half2 v3) {
    uint4 u;
    u.x = h2u(v0); u.y = h2u(v1); u.z = h2u(v2); u.w = h2u(v3);
    *(uint4*)p = u;
}

__device__ __forceinline__ void ldsm_x4(unsigned* r, unsigned addr) {
    asm volatile("ldmatrix.sync.aligned.m8n8.x4.shared.b16 {%0,%1,%2,%3},[%4];\n"
                 : "=r"(r[0]), "=r"(r[1]), "=r"(r[2]), "=r"(r[3]) : "r"(addr));
}

__device__ __forceinline__ void mma16816(float* d, const unsigned* a, const unsigned* b) {
    asm volatile("mma.sync.aligned.m16n8k16.row.col.f32.f16.f16.f32 "
                 "{%0,%1,%2,%3},{%4,%5,%6,%7},{%8,%9},{%0,%1,%2,%3};\n"
                 : "+f"(d[0]), "+f"(d[1]), "+f"(d[2]), "+f"(d[3])
                 : "r"(a[0]), "r"(a[1]), "r"(a[2]), "r"(a[3]), "r"(b[0]), "r"(b[1]));
}

__device__ __forceinline__ void cp16(unsigned s, const void* g) {
    asm volatile("cp.async.cg.shared.global [%0], [%1], 16;" :: "r"(s), "l"(g));
}
#define CP_COMMIT() asm volatile("cp.async.commit_group;" ::: "memory")
#define CP_WAIT0()  asm volatile("cp.async.wait_group 0;" ::: "memory")

// ---------------------------------------------------------------------------
// Kernel 1: 1x1-conv projections -> Q/K fp16 hi/lo (swizzled rows) + V fp16.
// Grid (64 s-tiles, 8 batches), 256 threads.
// ---------------------------------------------------------------------------
__global__ __launch_bounds__(256) void proj_kernel(const float* __restrict__ x,
                                                   const float* __restrict__ tw,
                                                   const float* __restrict__ pw)
{
    const int n  = blockIdx.y;
    const int s0 = blockIdx.x * 64;
    const int tid = threadIdx.x;
    const int ts = tid & 15;
    const int to = tid >> 4;

    __shared__ float xs [32][68];
    __shared__ float wts[128][33];
    __shared__ float wps[128][33];

    float qa[8][4], ka[8][4];
#pragma unroll
    for (int k = 0; k < 8; k++) {
#pragma unroll
        for (int i = 0; i < 4; i++) { qa[k][i] = 0.f; ka[k][i] = 0.f; }
    }

    const float* xb = x + (size_t)n * CIN * SQ;

    for (int c0 = 0; c0 < CIN; c0 += 32) {
        __syncthreads();
#pragma unroll
        for (int k = 0; k < 8; k++) {
            int idx = tid + 256 * k;
            int cc = idx >> 6;
            int ss = idx & 63;
            xs[cc][ss] = xb[(size_t)(c0 + cc) * SQ + s0 + ss];
        }
#pragma unroll
        for (int k = 0; k < 16; k++) {
            int idx = tid + 256 * k;
            int o = idx >> 5;
            int cc = idx & 31;
            wts[o][cc] = tw[o * CIN + c0 + cc];
            wps[o][cc] = pw[o * CIN + c0 + cc];
        }
        __syncthreads();

        // V: convert this x tile to fp16, write swizzled [n][c][s]
        {
            int cc = tid >> 3;            // 0..31
            int sj = tid & 7;             // 8-s chunk within the 64-s granule
            float4 f0 = *(const float4*)&xs[cc][sj * 8];
            float4 f1 = *(const float4*)&xs[cc][sj * 8 + 4];
            __half2 p0 = __floats2half2_rn(f0.x, f0.y);
            __half2 p1 = __floats2half2_rn(f0.z, f0.w);
            __half2 p2 = __floats2half2_rn(f1.x, f1.y);
            __half2 p3 = __floats2half2_rn(f1.z, f1.w);
            int c = c0 + cc;
            size_t off = ((size_t)n * CIN + c) * SQ + s0 + ((sj ^ (c & 7)) * 8);
            store4h2(&g_V[off], p0, p1, p2, p3);
        }

        // FMA
#pragma unroll
        for (int cc = 0; cc < 32; cc++) {
            float4 xv = *(const float4*)&xs[cc][ts * 4];
            float xr[4];
            xr[0] = xv.x; xr[1] = xv.y; xr[2] = xv.z; xr[3] = xv.w;
#pragma unroll
            for (int k = 0; k < 8; k++) {
                float twv = wts[to * 8 + k][cc];
                float pwv = wps[to * 8 + k][cc];
#pragma unroll
                for (int i = 0; i < 4; i++) {
                    qa[k][i] = fmaf(twv, xr[i], qa[k][i]);
                    ka[k][i] = fmaf(pwv, xr[i], ka[k][i]);
                }
            }
        }
    }
    // store Q,K [s][d] rows, 16B chunk `to` placed swizzled: half + (to&7)^(s&7)
#pragma unroll
    for (int i = 0; i < 4; i++) {
        int s = s0 + ts * 4 + i;
        size_t rowb = ((size_t)n * SQ + s) * CH;
        size_t base = rowb + (to >> 3) * 64 + (size_t)(((to & 7) ^ (s & 7)) * 8);
        __half2 qh[4], ql[4], kh[4], kl[4];
#pragma unroll
        for (int k2 = 0; k2 < 4; k2++) {
            cvt_hilo(qa[2 * k2][i], qa[2 * k2 + 1][i], qh[k2], ql[k2]);
            cvt_hilo(ka[2 * k2][i], ka[2 * k2 + 1][i], kh[k2], kl[k2]);
        }
        store4h2(&g_Qhi[base], qh[0], qh[1], qh[2], qh[3]);
        store4h2(&g_Qlo[base], ql[0], ql[1], ql[2], ql[3]);
        store4h2(&g_Khi[base], kh[0], kh[1], kh[2], kh[3]);
        store4h2(&g_Klo[base], kl[0], kl[1], kl[2], kl[3]);
    }
}

// ---------------------------------------------------------------------------
// Kernel 2: pipelined flash attention (FA-2 style, P in registers).
// BM=128, BN=64, d=128, dv=256. 8 warps; warp w owns m16 rows, full n.
// K/V double-buffered via cp.async; all operands pre-swizzled in global.
// SMEM byte offsets:
// ---------------------------------------------------------------------------
#define OQH 0
#define OQL 32768
#define OKHB(b) (65536 + (b) * 32768)
#define OKLB(b) (81920 + (b) * 32768)
#define OVB(b)  (131072 + (b) * 32768)
#define SM_TOTAL 196608

__global__ __launch_bounds__(256, 1) void flash_tc(const float* __restrict__ x,
                                                   float* __restrict__ out)
{
    extern __shared__ char smc[];
    const unsigned sb = (unsigned)__cvta_generic_to_shared(smc);

    const int n  = blockIdx.y;
    const int s0 = blockIdx.x * 128;
    const int tid = threadIdx.x;
    const int w  = tid >> 5;
    const int ln = tid & 31;
    const int m0 = w * 16;
    const int q3 = ln & 3;
    const int rq = ln >> 2;

    // ---- prologue: Q via cp.async (linear copy; swizzle baked in global) ----
#pragma unroll
    for (int i = 0; i < 8; i++) {
        int idx = tid + 256 * i;             // 0..2047
        int r = idx >> 4, ch = idx & 15;
        unsigned sd = sb + r * 256 + ch * 16;
        size_t gro = ((size_t)n * SQ + s0 + r) * CH + ch * 8;
        cp16(sd + OQH, g_Qhi + gro);
        cp16(sd + OQL, g_Qlo + gro);
    }
    // tile 0 K/V
    {
        const int t0 = 0;
#pragma unroll
        for (int i = 0; i < 4; i++) {
            int idx = tid + 256 * i;         // 0..1023
            int r = idx >> 4, ch = idx & 15;
            size_t gro = ((size_t)n * SQ + t0 + r) * CH + ch * 8;
            cp16(sb + OKHB(0) + r * 256 + ch * 16, g_Khi + gro);
            cp16(sb + OKLB(0) + r * 256 + ch * 16, g_Klo + gro);
        }
#pragma unroll
        for (int i = 0; i < 8; i++) {
            int idx = tid + 256 * i;         // 0..2047
            int r = idx >> 3, ch = idx & 7;
            cp16(sb + OVB(0) + r * 128 + ch * 16,
                 g_V + ((size_t)n * CIN + r) * SQ + t0 + ch * 8);
        }
    }
    CP_COMMIT();

    float oacc[32][4];
#pragma unroll
    for (int t = 0; t < 32; t++) {
#pragma unroll
        for (int i = 0; i < 4; i++) oacc[t][i] = 0.f;
    }
    float mrow0 = -1e30f, mrow1 = -1e30f;
    float lrow0 = 0.f, lrow1 = 0.f;

    // lane constants for swizzled LDSM addressing
    const int ar  = m0 + (ln & 15);          // A row (Q)
    const unsigned a_qbase = sb + ar * 256;  // + OQH/OQL added per use
    const int ah  = ln >> 4;                 // A k-chunk half
    const int arx = ar & 7;
    const int tr  = (ln & 7) + ((ln >> 4) & 1) * 8;  // B row within 16
    const int bh  = (ln >> 3) & 1;           // B k-chunk half
    const int brx = ln & 7;

    for (int it = 0; it < 64; it++) {
        CP_WAIT0();
        __syncthreads();
        if (it < 63) {                       // prefetch tile it+1
            const int t1 = (it + 1) << 6;
            const int b = (it + 1) & 1;
#pragma unroll
            for (int i = 0; i < 4; i++) {
                int idx = tid + 256 * i;
                int r = idx >> 4, ch = idx & 15;
                size_t gro = ((size_t)n * SQ + t1 + r) * CH + ch * 8;
                cp16(sb + OKHB(b) + r * 256 + ch * 16, g_Khi + gro);
                cp16(sb + OKLB(b) + r * 256 + ch * 16, g_Klo + gro);
            }
#pragma unroll
            for (int i = 0; i < 8; i++) {
                int idx = tid + 256 * i;
                int r = idx >> 3, ch = idx & 7;
                cp16(sb + OVB(b) + r * 128 + ch * 16,
                     g_V + ((size_t)n * CIN + r) * SQ + t1 + ch * 8);
            }
            CP_COMMIT();
        }
        const unsigned khb = sb + OKHB(it & 1);
        const unsigned klb = sb + OKLB(it & 1);
        const unsigned vb  = sb + OVB(it & 1);

        // ---- S = Q K^T (3-term split), warp: m16 x n64 x k128 ----
        float sacc[8][4];
#pragma unroll
        for (int t = 0; t < 8; t++) {
#pragma unroll
            for (int i = 0; i < 4; i++) sacc[t][i] = 0.f;
        }
#pragma unroll
        for (int k = 0; k < 8; k++) {
            const int cA = 2 * k + ah;
            const unsigned qoff = ((cA >> 3) << 7) + (((cA & 7) ^ arx) << 4);
            unsigned qh[4], ql4[4];
            ldsm_x4(qh,  a_qbase + OQH + qoff);
            ldsm_x4(ql4, a_qbase + OQL + qoff);
            const int cB = 2 * k + bh;
            const unsigned koff = tr * 256 + ((cB >> 3) << 7) + (((cB & 7) ^ brx) << 4);
#pragma unroll
            for (int nb = 0; nb < 4; nb++) {
                unsigned kh4[4], kl4[4];
                ldsm_x4(kh4, khb + nb * 4096 + koff);
                ldsm_x4(kl4, klb + nb * 4096 + koff);
                mma16816(sacc[2 * nb],     qh,  kh4);
                mma16816(sacc[2 * nb],     qh,  kl4);
                mma16816(sacc[2 * nb],     ql4, kh4);
                mma16816(sacc[2 * nb + 1], qh,  kh4 + 2);
                mma16816(sacc[2 * nb + 1], qh,  kl4 + 2);
                mma16816(sacc[2 * nb + 1], ql4, kh4 + 2);
            }
        }

        // ---- softmax: full row per warp, quad-shuffle reduce only ----
        float rm0 = -1e30f, rm1 = -1e30f;
#pragma unroll
        for (int nt = 0; nt < 8; nt++) {
            rm0 = fmaxf(rm0, fmaxf(sacc[nt][0], sacc[nt][1]));
            rm1 = fmaxf(rm1, fmaxf(sacc[nt][2], sacc[nt][3]));
        }
        rm0 = fmaxf(rm0, __shfl_xor_sync(0xffffffffu, rm0, 1));
        rm0 = fmaxf(rm0, __shfl_xor_sync(0xffffffffu, rm0, 2));
        rm1 = fmaxf(rm1, __shfl_xor_sync(0xffffffffu, rm1, 1));
        rm1 = fmaxf(rm1, __shfl_xor_sync(0xffffffffu, rm1, 2));
        const float mn0 = fmaxf(mrow0, rm0);
        const float mn1 = fmaxf(mrow1, rm1);
        const float al0 = __expf(mrow0 - mn0);
        const float al1 = __expf(mrow1 - mn1);
        mrow0 = mn0;
        mrow1 = mn1;

        float sum0 = 0.f, sum1 = 0.f;
#pragma unroll
        for (int nt = 0; nt < 8; nt++) {
            sacc[nt][0] = __expf(sacc[nt][0] - mn0);
            sacc[nt][1] = __expf(sacc[nt][1] - mn0);
            sacc[nt][2] = __expf(sacc[nt][2] - mn1);
            sacc[nt][3] = __expf(sacc[nt][3] - mn1);
            sum0 += sacc[nt][0] + sacc[nt][1];
            sum1 += sacc[nt][2] + sacc[nt][3];
        }
        sum0 += __shfl_xor_sync(0xffffffffu, sum0, 1);
        sum0 += __shfl_xor_sync(0xffffffffu, sum0, 2);
        sum1 += __shfl_xor_sync(0xffffffffu, sum1, 1);
        sum1 += __shfl_xor_sync(0xffffffffu, sum1, 2);
        lrow0 = lrow0 * al0 + sum0;
        lrow1 = lrow1 * al1 + sum1;

#pragma unroll
        for (int nt = 0; nt < 32; nt++) {
            oacc[nt][0] *= al0;
            oacc[nt][1] *= al0;
            oacc[nt][2] *= al1;
            oacc[nt][3] *= al1;
        }

        // ---- O += P V : P hi/lo packed from registers, V fp16 in SMEM ----
#pragma unroll
        for (int kc = 0; kc < 4; kc++) {
            unsigned ahh[4], alo[4];
            {
                __half2 h0 = __floats2half2_rn(sacc[2 * kc][0],     sacc[2 * kc][1]);
                __half2 h1 = __floats2half2_rn(sacc[2 * kc][2],     sacc[2 * kc][3]);
                __half2 h2 = __floats2half2_rn(sacc[2 * kc + 1][0], sacc[2 * kc + 1][1]);
                __half2 h3 = __floats2half2_rn(sacc[2 * kc + 1][2], sacc[2 * kc + 1][3]);
                float2 f0 = __half22float2(h0);
                float2 f1 = __half22float2(h1);
                float2 f2 = __half22float2(h2);
                float2 f3 = __half22float2(h3);
                ahh[0] = h2u(h0); ahh[1] = h2u(h1); ahh[2] = h2u(h2); ahh[3] = h2u(h3);
                alo[0] = h2u(__floats2half2_rn(sacc[2 * kc][0] - f0.x,
                                               sacc[2 * kc][1] - f0.y));
                alo[1] = h2u(__floats2half2_rn(sacc[2 * kc][2] - f1.x,
                                               sacc[2 * kc][3] - f1.y));
                alo[2] = h2u(__floats2half2_rn(sacc[2 * kc + 1][0] - f2.x,
                                               sacc[2 * kc + 1][1] - f2.y));
                alo[3] = h2u(__floats2half2_rn(sacc[2 * kc + 1][2] - f3.x,
                                               sacc[2 * kc + 1][3] - f3.y));
            }
            const int cV = 2 * kc + bh;      // 0..7
            const unsigned voff = tr * 128 + (((cV ^ brx) & 7) << 4);
#pragma unroll
            for (int nb = 0; nb < 16; nb++) {
                unsigned vh4[4];
                ldsm_x4(vh4, vb + nb * 2048 + voff);
                mma16816(oacc[2 * nb],     ahh, vh4);
                mma16816(oacc[2 * nb],     alo, vh4);
                mma16816(oacc[2 * nb + 1], ahh, vh4 + 2);
                mma16816(oacc[2 * nb + 1], alo, vh4 + 2);
            }
        }
    }

    // ---- epilogue: normalize, two-pass SMEM transpose, residual add ----
    const float inv0 = 1.0f / lrow0;
    const float inv1 = 1.0f / lrow1;
#pragma unroll
    for (int nt = 0; nt < 32; nt++) {
        oacc[nt][0] *= inv0;
        oacc[nt][1] *= inv0;
        oacc[nt][2] *= inv1;
        oacc[nt][3] *= inv1;
    }

    float* stg = (float*)smc;    // [128 s][132] fp32 = 67584 B, tiles are dead
    const int cl0 = tid & 127;
    const int sg  = tid >> 7;    // 0,1 : s-half
    for (int pass = 0; pass < 2; pass++) {
        __syncthreads();
#pragma unroll
        for (int nt2 = 0; nt2 < 16; nt2++) {
            int nt = pass * 16 + nt2;
            int cl = nt2 * 8 + 2 * q3;
            *(float2*)&stg[(m0 + rq) * 132 + cl] =
                make_float2(oacc[nt][0], oacc[nt][1]);
            *(float2*)&stg[(m0 + rq + 8) * 132 + cl] =
                make_float2(oacc[nt][2], oacc[nt][3]);
        }
        __syncthreads();
        int c = pass * 128 + cl0;
        const float* xb = x   + ((size_t)n * CIN + c) * SQ + s0 + sg * 64;
        float*       ob = out + ((size_t)n * CIN + c) * SQ + s0 + sg * 64;
#pragma unroll
        for (int ss = 0; ss < 64; ss += 4) {
            float4 xv = *(const float4*)&xb[ss];
            float4 r;
            r.x = xv.x + stg[(sg * 64 + ss + 0) * 132 + cl0];
            r.y = xv.y + stg[(sg * 64 + ss + 1) * 132 + cl0];
            r.z = xv.z + stg[(sg * 64 + ss + 2) * 132 + cl0];
            r.w = xv.w + stg[(sg * 64 + ss + 3) * 132 + cl0];
            *(float4*)&ob[ss] = r;
        }
    }
}

// ---------------------------------------------------------------------------
extern "C" void kernel_launch(void* const* d_in, const int* in_sizes, int n_in,
                              void* d_out, int out_size)
{
    const float* x  = (const float*)d_in[0];   // [8,256,64,64]
    const float* tw = (const float*)d_in[1];   // [128,256]
    const float* pw = (const float*)d_in[2];   // [128,256]
    float* out = (float*)d_out;

    cudaFuncSetAttribute(flash_tc,
                         cudaFuncAttributeMaxDynamicSharedMemorySize, SM_TOTAL);

    proj_kernel<<<dim3(64, 8), 256>>>(x, tw, pw);
    flash_tc<<<dim3(32, 8), 256, SM_TOTAL>>>(x, out);
}

// round 13
// speedup vs baseline: 6.1705x; 1.1941x over previous
#include <cuda_runtime.h>
#include <cuda_fp16.h>
#include <math.h>

#define SQ  4096   // H*W
#define CIN 256    // C
#define CH  128    // C/2
#define NB  8      // batch

// Scratch: Q,K fp16 hi/lo [n][s][d] rows pre-swizzled; V fp16 [n][c][s] granule-swizzled
__device__ __half g_Qhi[(size_t)NB * SQ * CH];
__device__ __half g_Qlo[(size_t)NB * SQ * CH];
__device__ __half g_Khi[(size_t)NB * SQ * CH];
__device__ __half g_Klo[(size_t)NB * SQ * CH];
__device__ __half g_V  [(size_t)NB * CIN * SQ];

// ---------------------------------------------------------------------------
// helpers
// ---------------------------------------------------------------------------
union H2U { __half2 h; unsigned u; };

__device__ __forceinline__ unsigned h2u(__half2 v) { H2U c; c.h = v; return c.u; }

__device__ __forceinline__ void cvt_hilo(float a, float b, __half2& hi, __half2& lo) {
    __half ha = __float2half_rn(a);
    __half hb = __float2half_rn(b);
    hi = __halves2half2(ha, hb);
    lo = __halves2half2(__float2half_rn(a - __half2float(ha)),
                        __float2half_rn(b - __half2float(hb)));
}

__device__ __forceinline__ void store4h2(__half* p, __half2 v0, __half2 v1,
                                         __half2 v2, __half2 v3) {
    uint4 u;
    u.x = h2u(v0); u.y = h2u(v1); u.z = h2u(v2); u.w = h2u(v3);
    *(uint4*)p = u;
}

__device__ __forceinline__ void ldsm_x4(unsigned* r, unsigned addr) {
    asm volatile("ldmatrix.sync.aligned.m8n8.x4.shared.b16 {%0,%1,%2,%3},[%4];\n"
                 : "=r"(r[0]), "=r"(r[1]), "=r"(r[2]), "=r"(r[3]) : "r"(addr));
}

__device__ __forceinline__ void mma16816(float* d, const unsigned* a, const unsigned* b) {
    asm volatile("mma.sync.aligned.m16n8k16.row.col.f32.f16.f16.f32 "
                 "{%0,%1,%2,%3},{%4,%5,%6,%7},{%8,%9},{%0,%1,%2,%3};\n"
                 : "+f"(d[0]), "+f"(d[1]), "+f"(d[2]), "+f"(d[3])
                 : "r"(a[0]), "r"(a[1]), "r"(a[2]), "r"(a[3]), "r"(b[0]), "r"(b[1]));
}

__device__ __forceinline__ void cp16(unsigned s, const void* g) {
    asm volatile("cp.async.cg.shared.global [%0], [%1], 16;" :: "r"(s), "l"(g));
}
#define CP_COMMIT() asm volatile("cp.async.commit_group;" ::: "memory")
#define CP_WAIT0()  asm volatile("cp.async.wait_group 0;" ::: "memory")

// ---------------------------------------------------------------------------
// Kernel 1: 1x1-conv projections -> Q/K fp16 hi/lo (swizzled rows) + V fp16.
// Grid (64 s-tiles, 8 batches), 256 threads.
// ---------------------------------------------------------------------------
__global__ __launch_bounds__(256) void proj_kernel(const float* __restrict__ x,
                                                   const float* __restrict__ tw,
                                                   const float* __restrict__ pw)
{
    const int n  = blockIdx.y;
    const int s0 = blockIdx.x * 64;
    const int tid = threadIdx.x;
    const int ts = tid & 15;
    const int to = tid >> 4;

    __shared__ float xs [32][68];
    __shared__ float wts[128][33];
    __shared__ float wps[128][33];

    float qa[8][4], ka[8][4];
#pragma unroll
    for (int k = 0; k < 8; k++) {
#pragma unroll
        for (int i = 0; i < 4; i++) { qa[k][i] = 0.f; ka[k][i] = 0.f; }
    }

    const float* xb = x + (size_t)n * CIN * SQ;

    for (int c0 = 0; c0 < CIN; c0 += 32) {
        __syncthreads();
#pragma unroll
        for (int k = 0; k < 8; k++) {
            int idx = tid + 256 * k;
            int cc = idx >> 6;
            int ss = idx & 63;
            xs[cc][ss] = xb[(size_t)(c0 + cc) * SQ + s0 + ss];
        }
#pragma unroll
        for (int k = 0; k < 16; k++) {
            int idx = tid + 256 * k;
            int o = idx >> 5;
            int cc = idx & 31;
            wts[o][cc] = tw[o * CIN + c0 + cc];
            wps[o][cc] = pw[o * CIN + c0 + cc];
        }
        __syncthreads();

        // V: convert this x tile to fp16, write swizzled [n][c][s]
        {
            int cc = tid >> 3;            // 0..31
            int sj = tid & 7;             // 8-s chunk within the 64-s granule
            float4 f0 = *(const float4*)&xs[cc][sj * 8];
            float4 f1 = *(const float4*)&xs[cc][sj * 8 + 4];
            __half2 p0 = __floats2half2_rn(f0.x, f0.y);
            __half2 p1 = __floats2half2_rn(f0.z, f0.w);
            __half2 p2 = __floats2half2_rn(f1.x, f1.y);
            __half2 p3 = __floats2half2_rn(f1.z, f1.w);
            int c = c0 + cc;
            size_t off = ((size_t)n * CIN + c) * SQ + s0 + ((sj ^ (c & 7)) * 8);
            store4h2(&g_V[off], p0, p1, p2, p3);
        }

        // FMA
#pragma unroll
        for (int cc = 0; cc < 32; cc++) {
            float4 xv = *(const float4*)&xs[cc][ts * 4];
            float xr[4];
            xr[0] = xv.x; xr[1] = xv.y; xr[2] = xv.z; xr[3] = xv.w;
#pragma unroll
            for (int k = 0; k < 8; k++) {
                float twv = wts[to * 8 + k][cc];
                float pwv = wps[to * 8 + k][cc];
#pragma unroll
                for (int i = 0; i < 4; i++) {
                    qa[k][i] = fmaf(twv, xr[i], qa[k][i]);
                    ka[k][i] = fmaf(pwv, xr[i], ka[k][i]);
                }
            }
        }
    }
    // store Q,K [s][d] rows, 16B chunk `to` placed swizzled: half + (to&7)^(s&7)
#pragma unroll
    for (int i = 0; i < 4; i++) {
        int s = s0 + ts * 4 + i;
        size_t rowb = ((size_t)n * SQ + s) * CH;
        size_t base = rowb + (to >> 3) * 64 + (size_t)(((to & 7) ^ (s & 7)) * 8);
        __half2 qh[4], ql[4], kh[4], kl[4];
#pragma unroll
        for (int k2 = 0; k2 < 4; k2++) {
            cvt_hilo(qa[2 * k2][i], qa[2 * k2 + 1][i], qh[k2], ql[k2]);
            cvt_hilo(ka[2 * k2][i], ka[2 * k2 + 1][i], kh[k2], kl[k2]);
        }
        store4h2(&g_Qhi[base], qh[0], qh[1], qh[2], qh[3]);
        store4h2(&g_Qlo[base], ql[0], ql[1], ql[2], ql[3]);
        store4h2(&g_Khi[base], kh[0], kh[1], kh[2], kh[3]);
        store4h2(&g_Klo[base], kl[0], kl[1], kl[2], kl[3]);
    }
}

// ---------------------------------------------------------------------------
// Kernel 2: pipelined flash attention (FA-2 style, P in registers).
// BM=128, BN=64, d=128, dv=256. 8 warps; warp w owns m16 rows, full n.
// QK: 3-term fp16 split. PV: single-term (P fp16, V fp16).
// K/V double-buffered via cp.async; all operands pre-swizzled in global.
// ---------------------------------------------------------------------------
#define OQH 0
#define OQL 32768
#define OKHB(b) (65536 + (b) * 32768)
#define OKLB(b) (81920 + (b) * 32768)
#define OVB(b)  (131072 + (b) * 32768)
#define SM_TOTAL 196608

__global__ __launch_bounds__(256, 1) void flash_tc(const float* __restrict__ x,
                                                   float* __restrict__ out)
{
    extern __shared__ char smc[];
    const unsigned sb = (unsigned)__cvta_generic_to_shared(smc);

    const int n  = blockIdx.y;
    const int s0 = blockIdx.x * 128;
    const int tid = threadIdx.x;
    const int w  = tid >> 5;
    const int ln = tid & 31;
    const int m0 = w * 16;
    const int q3 = ln & 3;
    const int rq = ln >> 2;

    // ---- prologue: Q via cp.async (linear copy; swizzle baked in global) ----
#pragma unroll
    for (int i = 0; i < 8; i++) {
        int idx = tid + 256 * i;             // 0..2047
        int r = idx >> 4, ch = idx & 15;
        unsigned sd = sb + r * 256 + ch * 16;
        size_t gro = ((size_t)n * SQ + s0 + r) * CH + ch * 8;
        cp16(sd + OQH, g_Qhi + gro);
        cp16(sd + OQL, g_Qlo + gro);
    }
    // tile 0 K/V
    {
        const int t0 = 0;
#pragma unroll
        for (int i = 0; i < 4; i++) {
            int idx = tid + 256 * i;         // 0..1023
            int r = idx >> 4, ch = idx & 15;
            size_t gro = ((size_t)n * SQ + t0 + r) * CH + ch * 8;
            cp16(sb + OKHB(0) + r * 256 + ch * 16, g_Khi + gro);
            cp16(sb + OKLB(0) + r * 256 + ch * 16, g_Klo + gro);
        }
#pragma unroll
        for (int i = 0; i < 8; i++) {
            int idx = tid + 256 * i;         // 0..2047
            int r = idx >> 3, ch = idx & 7;
            cp16(sb + OVB(0) + r * 128 + ch * 16,
                 g_V + ((size_t)n * CIN + r) * SQ + t0 + ch * 8);
        }
    }
    CP_COMMIT();

    float oacc[32][4];
#pragma unroll
    for (int t = 0; t < 32; t++) {
#pragma unroll
        for (int i = 0; i < 4; i++) oacc[t][i] = 0.f;
    }
    float mrow0 = -1e30f, mrow1 = -1e30f;
    float lrow0 = 0.f, lrow1 = 0.f;

    // lane constants for swizzled LDSM addressing
    const int ar  = m0 + (ln & 15);          // A row (Q)
    const unsigned a_qbase = sb + ar * 256;  // + OQH/OQL added per use
    const int ah  = ln >> 4;                 // A k-chunk half
    const int arx = ar & 7;
    const int tr  = (ln & 7) + ((ln >> 4) & 1) * 8;  // B row within 16
    const int bh  = (ln >> 3) & 1;           // B k-chunk half
    const int brx = ln & 7;

    for (int it = 0; it < 64; it++) {
        CP_WAIT0();
        __syncthreads();
        if (it < 63) {                       // prefetch tile it+1
            const int t1 = (it + 1) << 6;
            const int b = (it + 1) & 1;
#pragma unroll
            for (int i = 0; i < 4; i++) {
                int idx = tid + 256 * i;
                int r = idx >> 4, ch = idx & 15;
                size_t gro = ((size_t)n * SQ + t1 + r) * CH + ch * 8;
                cp16(sb + OKHB(b) + r * 256 + ch * 16, g_Khi + gro);
                cp16(sb + OKLB(b) + r * 256 + ch * 16, g_Klo + gro);
            }
#pragma unroll
            for (int i = 0; i < 8; i++) {
                int idx = tid + 256 * i;
                int r = idx >> 3, ch = idx & 7;
                cp16(sb + OVB(b) + r * 128 + ch * 16,
                     g_V + ((size_t)n * CIN + r) * SQ + t1 + ch * 8);
            }
            CP_COMMIT();
        }
        const unsigned khb = sb + OKHB(it & 1);
        const unsigned klb = sb + OKLB(it & 1);
        const unsigned vb  = sb + OVB(it & 1);

        // ---- S = Q K^T (3-term split), warp: m16 x n64 x k128 ----
        float sacc[8][4];
#pragma unroll
        for (int t = 0; t < 8; t++) {
#pragma unroll
            for (int i = 0; i < 4; i++) sacc[t][i] = 0.f;
        }
#pragma unroll
        for (int k = 0; k < 8; k++) {
            const int cA = 2 * k + ah;
            const unsigned qoff = ((cA >> 3) << 7) + (((cA & 7) ^ arx) << 4);
            unsigned qh[4], ql4[4];
            ldsm_x4(qh,  a_qbase + OQH + qoff);
            ldsm_x4(ql4, a_qbase + OQL + qoff);
            const int cB = 2 * k + bh;
            const unsigned koff = tr * 256 + ((cB >> 3) << 7) + (((cB & 7) ^ brx) << 4);
#pragma unroll
            for (int nb = 0; nb < 4; nb++) {
                unsigned kh4[4], kl4[4];
                ldsm_x4(kh4, khb + nb * 4096 + koff);
                ldsm_x4(kl4, klb + nb * 4096 + koff);
                mma16816(sacc[2 * nb],     qh,  kh4);
                mma16816(sacc[2 * nb],     qh,  kl4);
                mma16816(sacc[2 * nb],     ql4, kh4);
                mma16816(sacc[2 * nb + 1], qh,  kh4 + 2);
                mma16816(sacc[2 * nb + 1], qh,  kl4 + 2);
                mma16816(sacc[2 * nb + 1], ql4, kh4 + 2);
            }
        }

        // ---- softmax: full row per warp, quad-shuffle reduce only ----
        float rm0 = -1e30f, rm1 = -1e30f;
#pragma unroll
        for (int nt = 0; nt < 8; nt++) {
            rm0 = fmaxf(rm0, fmaxf(sacc[nt][0], sacc[nt][1]));
            rm1 = fmaxf(rm1, fmaxf(sacc[nt][2], sacc[nt][3]));
        }
        rm0 = fmaxf(rm0, __shfl_xor_sync(0xffffffffu, rm0, 1));
        rm0 = fmaxf(rm0, __shfl_xor_sync(0xffffffffu, rm0, 2));
        rm1 = fmaxf(rm1, __shfl_xor_sync(0xffffffffu, rm1, 1));
        rm1 = fmaxf(rm1, __shfl_xor_sync(0xffffffffu, rm1, 2));
        const float mn0 = fmaxf(mrow0, rm0);
        const float mn1 = fmaxf(mrow1, rm1);
        const float al0 = __expf(mrow0 - mn0);
        const float al1 = __expf(mrow1 - mn1);
        mrow0 = mn0;
        mrow1 = mn1;

        float sum0 = 0.f, sum1 = 0.f;
#pragma unroll
        for (int nt = 0; nt < 8; nt++) {
            sacc[nt][0] = __expf(sacc[nt][0] - mn0);
            sacc[nt][1] = __expf(sacc[nt][1] - mn0);
            sacc[nt][2] = __expf(sacc[nt][2] - mn1);
            sacc[nt][3] = __expf(sacc[nt][3] - mn1);
            sum0 += sacc[nt][0] + sacc[nt][1];
            sum1 += sacc[nt][2] + sacc[nt][3];
        }
        sum0 += __shfl_xor_sync(0xffffffffu, sum0, 1);
        sum0 += __shfl_xor_sync(0xffffffffu, sum0, 2);
        sum1 += __shfl_xor_sync(0xffffffffu, sum1, 1);
        sum1 += __shfl_xor_sync(0xffffffffu, sum1, 2);
        lrow0 = lrow0 * al0 + sum0;
        lrow1 = lrow1 * al1 + sum1;

        // rescale O only when some row's max actually moved (exp(0)==1 exactly)
        if (__ballot_sync(0xffffffffu, (al0 != 1.0f) || (al1 != 1.0f))) {
#pragma unroll
            for (int nt = 0; nt < 32; nt++) {
                oacc[nt][0] *= al0;
                oacc[nt][1] *= al0;
                oacc[nt][2] *= al1;
                oacc[nt][3] *= al1;
            }
        }

        // ---- O += P V : single-term, P fp16 from registers, V fp16 in SMEM ----
#pragma unroll
        for (int kc = 0; kc < 4; kc++) {
            unsigned ahh[4];
            ahh[0] = h2u(__floats2half2_rn(sacc[2 * kc][0],     sacc[2 * kc][1]));
            ahh[1] = h2u(__floats2half2_rn(sacc[2 * kc][2],     sacc[2 * kc][3]));
            ahh[2] = h2u(__floats2half2_rn(sacc[2 * kc + 1][0], sacc[2 * kc + 1][1]));
            ahh[3] = h2u(__floats2half2_rn(sacc[2 * kc + 1][2], sacc[2 * kc + 1][3]));
            const int cV = 2 * kc + bh;      // 0..7
            const unsigned voff = tr * 128 + (((cV ^ brx) & 7) << 4);
#pragma unroll
            for (int nb = 0; nb < 16; nb++) {
                unsigned vh4[4];
                ldsm_x4(vh4, vb + nb * 2048 + voff);
                mma16816(oacc[2 * nb],     ahh, vh4);
                mma16816(oacc[2 * nb + 1], ahh, vh4 + 2);
            }
        }
    }

    // ---- epilogue: normalize, two-pass SMEM transpose, residual add ----
    const float inv0 = 1.0f / lrow0;
    const float inv1 = 1.0f / lrow1;
#pragma unroll
    for (int nt = 0; nt < 32; nt++) {
        oacc[nt][0] *= inv0;
        oacc[nt][1] *= inv0;
        oacc[nt][2] *= inv1;
        oacc[nt][3] *= inv1;
    }

    float* stg = (float*)smc;    // [128 s][132] fp32 = 67584 B, tiles are dead
    const int cl0 = tid & 127;
    const int sg  = tid >> 7;    // 0,1 : s-half
    for (int pass = 0; pass < 2; pass++) {
        __syncthreads();
#pragma unroll
        for (int nt2 = 0; nt2 < 16; nt2++) {
            int nt = pass * 16 + nt2;
            int cl = nt2 * 8 + 2 * q3;
            *(float2*)&stg[(m0 + rq) * 132 + cl] =
                make_float2(oacc[nt][0], oacc[nt][1]);
            *(float2*)&stg[(m0 + rq + 8) * 132 + cl] =
                make_float2(oacc[nt][2], oacc[nt][3]);
        }
        __syncthreads();
        int c = pass * 128 + cl0;
        const float* xb = x   + ((size_t)n * CIN + c) * SQ + s0 + sg * 64;
        float*       ob = out + ((size_t)n * CIN + c) * SQ + s0 + sg * 64;
#pragma unroll
        for (int ss = 0; ss < 64; ss += 4) {
            float4 xv = *(const float4*)&xb[ss];
            float4 r;
            r.x = xv.x + stg[(sg * 64 + ss + 0) * 132 + cl0];
            r.y = xv.y + stg[(sg * 64 + ss + 1) * 132 + cl0];
            r.z = xv.z + stg[(sg * 64 + ss + 2) * 132 + cl0];
            r.w = xv.w + stg[(sg * 64 + ss + 3) * 132 + cl0];
            *(float4*)&ob[ss] = r;
        }
    }
}

// ---------------------------------------------------------------------------
extern "C" void kernel_launch(void* const* d_in, const int* in_sizes, int n_in,
                              void* d_out, int out_size)
{
    const float* x  = (const float*)d_in[0];   // [8,256,64,64]
    const float* tw = (const float*)d_in[1];   // [128,256]
    const float* pw = (const float*)d_in[2];   // [128,256]
    float* out = (float*)d_out;

    cudaFuncSetAttribute(flash_tc,
                         cudaFuncAttributeMaxDynamicSharedMemorySize, SM_TOTAL);

    proj_kernel<<<dim3(64, 8), 256>>>(x, tw, pw);
    flash_tc<<<dim3(32, 8), 256, SM_TOTAL>>>(x, out);
}

// round 14
// speedup vs baseline: 6.2085x; 1.0062x over previous
#include <cuda_runtime.h>
#include <cuda_fp16.h>
#include <math.h>

#define SQ  4096   // H*W
#define CIN 256    // C
#define CH  128    // C/2
#define NB  8      // batch

// Scratch: Q,K fp16 hi/lo [n][s][d] rows pre-swizzled; V fp16 [n][c][s] granule-swizzled
__device__ __half g_Qhi[(size_t)NB * SQ * CH];
__device__ __half g_Qlo[(size_t)NB * SQ * CH];
__device__ __half g_Khi[(size_t)NB * SQ * CH];
__device__ __half g_Klo[(size_t)NB * SQ * CH];
__device__ __half g_V  [(size_t)NB * CIN * SQ];

// ---------------------------------------------------------------------------
// helpers
// ---------------------------------------------------------------------------
union H2U { __half2 h; unsigned u; };

__device__ __forceinline__ unsigned h2u(__half2 v) { H2U c; c.h = v; return c.u; }

__device__ __forceinline__ void cvt_hilo(float a, float b, __half2& hi, __half2& lo) {
    __half ha = __float2half_rn(a);
    __half hb = __float2half_rn(b);
    hi = __halves2half2(ha, hb);
    lo = __halves2half2(__float2half_rn(a - __half2float(ha)),
                        __float2half_rn(b - __half2float(hb)));
}

__device__ __forceinline__ void store4h2(__half* p, __half2 v0, __half2 v1,
                                         __half2 v2, __half2 v3) {
    uint4 u;
    u.x = h2u(v0); u.y = h2u(v1); u.z = h2u(v2); u.w = h2u(v3);
    *(uint4*)p = u;
}

__device__ __forceinline__ void ldsm_x4(unsigned* r, unsigned addr) {
    asm volatile("ldmatrix.sync.aligned.m8n8.x4.shared.b16 {%0,%1,%2,%3},[%4];\n"
                 : "=r"(r[0]), "=r"(r[1]), "=r"(r[2]), "=r"(r[3]) : "r"(addr));
}

__device__ __forceinline__ void mma16816(float* d, const unsigned* a, const unsigned* b) {
    asm volatile("mma.sync.aligned.m16n8k16.row.col.f32.f16.f16.f32 "
                 "{%0,%1,%2,%3},{%4,%5,%6,%7},{%8,%9},{%0,%1,%2,%3};\n"
                 : "+f"(d[0]), "+f"(d[1]), "+f"(d[2]), "+f"(d[3])
                 : "r"(a[0]), "r"(a[1]), "r"(a[2]), "r"(a[3]), "r"(b[0]), "r"(b[1]));
}

__device__ __forceinline__ void cp16(unsigned s, const void* g) {
    asm volatile("cp.async.cg.shared.global [%0], [%1], 16;" :: "r"(s), "l"(g));
}
#define CP_COMMIT() asm volatile("cp.async.commit_group;" ::: "memory")
#define CP_WAIT0()  asm volatile("cp.async.wait_group 0;" ::: "memory")

// ---------------------------------------------------------------------------
// Kernel 1: 1x1-conv projections -> Q/K fp16 hi/lo (swizzled rows) + V fp16.
// Grid (64 s-tiles, 8 batches), 256 threads.
// ---------------------------------------------------------------------------
__global__ __launch_bounds__(256) void proj_kernel(const float* __restrict__ x,
                                                   const float* __restrict__ tw,
                                                   const float* __restrict__ pw)
{
    const int n  = blockIdx.y;
    const int s0 = blockIdx.x * 64;
    const int tid = threadIdx.x;
    const int ts = tid & 15;
    const int to = tid >> 4;

    __shared__ float xs [32][68];
    __shared__ float wts[128][33];
    __shared__ float wps[128][33];

    float qa[8][4], ka[8][4];
#pragma unroll
    for (int k = 0; k < 8; k++) {
#pragma unroll
        for (int i = 0; i < 4; i++) { qa[k][i] = 0.f; ka[k][i] = 0.f; }
    }

    const float* xb = x + (size_t)n * CIN * SQ;

    for (int c0 = 0; c0 < CIN; c0 += 32) {
        __syncthreads();
#pragma unroll
        for (int k = 0; k < 8; k++) {
            int idx = tid + 256 * k;
            int cc = idx >> 6;
            int ss = idx & 63;
            xs[cc][ss] = xb[(size_t)(c0 + cc) * SQ + s0 + ss];
        }
#pragma unroll
        for (int k = 0; k < 16; k++) {
            int idx = tid + 256 * k;
            int o = idx >> 5;
            int cc = idx & 31;
            wts[o][cc] = tw[o * CIN + c0 + cc];
            wps[o][cc] = pw[o * CIN + c0 + cc];
        }
        __syncthreads();

        // V: convert this x tile to fp16, write swizzled [n][c][s]
        {
            int cc = tid >> 3;            // 0..31
            int sj = tid & 7;             // 8-s chunk within the 64-s granule
            float4 f0 = *(const float4*)&xs[cc][sj * 8];
            float4 f1 = *(const float4*)&xs[cc][sj * 8 + 4];
            __half2 p0 = __floats2half2_rn(f0.x, f0.y);
            __half2 p1 = __floats2half2_rn(f0.z, f0.w);
            __half2 p2 = __floats2half2_rn(f1.x, f1.y);
            __half2 p3 = __floats2half2_rn(f1.z, f1.w);
            int c = c0 + cc;
            size_t off = ((size_t)n * CIN + c) * SQ + s0 + ((sj ^ (c & 7)) * 8);
            store4h2(&g_V[off], p0, p1, p2, p3);
        }

        // FMA
#pragma unroll
        for (int cc = 0; cc < 32; cc++) {
            float4 xv = *(const float4*)&xs[cc][ts * 4];
            float xr[4];
            xr[0] = xv.x; xr[1] = xv.y; xr[2] = xv.z; xr[3] = xv.w;
#pragma unroll
            for (int k = 0; k < 8; k++) {
                float twv = wts[to * 8 + k][cc];
                float pwv = wps[to * 8 + k][cc];
#pragma unroll
                for (int i = 0; i < 4; i++) {
                    qa[k][i] = fmaf(twv, xr[i], qa[k][i]);
                    ka[k][i] = fmaf(pwv, xr[i], ka[k][i]);
                }
            }
        }
    }
    // store Q,K [s][d] rows, 16B chunk `to` placed swizzled: half + (to&7)^(s&7)
#pragma unroll
    for (int i = 0; i < 4; i++) {
        int s = s0 + ts * 4 + i;
        size_t rowb = ((size_t)n * SQ + s) * CH;
        size_t base = rowb + (to >> 3) * 64 + (size_t)(((to & 7) ^ (s & 7)) * 8);
        __half2 qh[4], ql[4], kh[4], kl[4];
#pragma unroll
        for (int k2 = 0; k2 < 4; k2++) {
            cvt_hilo(qa[2 * k2][i], qa[2 * k2 + 1][i], qh[k2], ql[k2]);
            cvt_hilo(ka[2 * k2][i], ka[2 * k2 + 1][i], kh[k2], kl[k2]);
        }
        store4h2(&g_Qhi[base], qh[0], qh[1], qh[2], qh[3]);
        store4h2(&g_Qlo[base], ql[0], ql[1], ql[2], ql[3]);
        store4h2(&g_Khi[base], kh[0], kh[1], kh[2], kh[3]);
        store4h2(&g_Klo[base], kl[0], kl[1], kl[2], kl[3]);
    }
}

// ---------------------------------------------------------------------------
// Kernel 2: pipelined flash attention (FA-2 style, P in registers).
// BM=128, BN=64, d=128, dv=256. 8 warps; warp w owns m16 rows, full n.
// QK: 3-term fp16 split. PV: single-term (P fp16, V fp16).
// K/V double-buffered via cp.async; all operands pre-swizzled in global.
// ---------------------------------------------------------------------------
#define OQH 0
#define OQL 32768
#define OKHB(b) (65536 + (b) * 32768)
#define OKLB(b) (81920 + (b) * 32768)
#define OVB(b)  (131072 + (b) * 32768)
#define SM_TOTAL 196608

__global__ __launch_bounds__(256, 1) void flash_tc(const float* __restrict__ x,
                                                   float* __restrict__ out)
{
    extern __shared__ char smc[];
    const unsigned sb = (unsigned)__cvta_generic_to_shared(smc);

    const int n  = blockIdx.y;
    const int s0 = blockIdx.x * 128;
    const int tid = threadIdx.x;
    const int w  = tid >> 5;
    const int ln = tid & 31;
    const int m0 = w * 16;
    const int q3 = ln & 3;
    const int rq = ln >> 2;

    // ---- prologue: Q via cp.async (linear copy; swizzle baked in global) ----
#pragma unroll
    for (int i = 0; i < 8; i++) {
        int idx = tid + 256 * i;             // 0..2047
        int r = idx >> 4, ch = idx & 15;
        unsigned sd = sb + r * 256 + ch * 16;
        size_t gro = ((size_t)n * SQ + s0 + r) * CH + ch * 8;
        cp16(sd + OQH, g_Qhi + gro);
        cp16(sd + OQL, g_Qlo + gro);
    }
    // tile 0 K/V
    {
        const int t0 = 0;
#pragma unroll
        for (int i = 0; i < 4; i++) {
            int idx = tid + 256 * i;         // 0..1023
            int r = idx >> 4, ch = idx & 15;
            size_t gro = ((size_t)n * SQ + t0 + r) * CH + ch * 8;
            cp16(sb + OKHB(0) + r * 256 + ch * 16, g_Khi + gro);
            cp16(sb + OKLB(0) + r * 256 + ch * 16, g_Klo + gro);
        }
#pragma unroll
        for (int i = 0; i < 8; i++) {
            int idx = tid + 256 * i;         // 0..2047
            int r = idx >> 3, ch = idx & 7;
            cp16(sb + OVB(0) + r * 128 + ch * 16,
                 g_V + ((size_t)n * CIN + r) * SQ + t0 + ch * 8);
        }
    }
    CP_COMMIT();

    float oacc[32][4];
#pragma unroll
    for (int t = 0; t < 32; t++) {
#pragma unroll
        for (int i = 0; i < 4; i++) oacc[t][i] = 0.f;
    }
    float mrow0 = -1e30f, mrow1 = -1e30f;
    float lrow0 = 0.f, lrow1 = 0.f;

    // lane constants for swizzled LDSM addressing
    const int ar  = m0 + (ln & 15);          // A row (Q)
    const unsigned a_qbase = sb + ar * 256;  // + OQH/OQL added per use
    const int ah  = ln >> 4;                 // A k-chunk half
    const int arx = ar & 7;
    const int tr  = (ln & 7) + ((ln >> 4) & 1) * 8;  // B row within 16
    const int bh  = (ln >> 3) & 1;           // B k-chunk half
    const int brx = ln & 7;

    for (int it = 0; it < 64; it++) {
        CP_WAIT0();
        __syncthreads();
        if (it < 63) {                       // prefetch tile it+1
            const int t1 = (it + 1) << 6;
            const int b = (it + 1) & 1;
#pragma unroll
            for (int i = 0; i < 4; i++) {
                int idx = tid + 256 * i;
                int r = idx >> 4, ch = idx & 15;
                size_t gro = ((size_t)n * SQ + t1 + r) * CH + ch * 8;
                cp16(sb + OKHB(b) + r * 256 + ch * 16, g_Khi + gro);
                cp16(sb + OKLB(b) + r * 256 + ch * 16, g_Klo + gro);
            }
#pragma unroll
            for (int i = 0; i < 8; i++) {
                int idx = tid + 256 * i;
                int r = idx >> 3, ch = idx & 7;
                cp16(sb + OVB(b) + r * 128 + ch * 16,
                     g_V + ((size_t)n * CIN + r) * SQ + t1 + ch * 8);
            }
            CP_COMMIT();
        }
        const unsigned khb = sb + OKHB(it & 1);
        const unsigned klb = sb + OKLB(it & 1);
        const unsigned vb  = sb + OVB(it & 1);

        // ---- S = Q K^T (3-term split), warp: m16 x n64 x k128 ----
        float sacc[8][4];
#pragma unroll
        for (int t = 0; t < 8; t++) {
#pragma unroll
            for (int i = 0; i < 4; i++) sacc[t][i] = 0.f;
        }
#pragma unroll
        for (int k = 0; k < 8; k++) {
            const int cA = 2 * k + ah;
            const unsigned qoff = ((cA >> 3) << 7) + (((cA & 7) ^ arx) << 4);
            unsigned qh[4], ql4[4];
            ldsm_x4(qh,  a_qbase + OQH + qoff);
            ldsm_x4(ql4, a_qbase + OQL + qoff);
            const int cB = 2 * k + bh;
            const unsigned koff = tr * 256 + ((cB >> 3) << 7) + (((cB & 7) ^ brx) << 4);
#pragma unroll
            for (int nb = 0; nb < 4; nb++) {
                unsigned kh4[4], kl4[4];
                ldsm_x4(kh4, khb + nb * 4096 + koff);
                ldsm_x4(kl4, klb + nb * 4096 + koff);
                mma16816(sacc[2 * nb],     qh,  kh4);
                mma16816(sacc[2 * nb],     qh,  kl4);
                mma16816(sacc[2 * nb],     ql4, kh4);
                mma16816(sacc[2 * nb + 1], qh,  kh4 + 2);
                mma16816(sacc[2 * nb + 1], qh,  kl4 + 2);
                mma16816(sacc[2 * nb + 1], ql4, kh4 + 2);
            }
        }

        // ---- softmax: full row per warp, quad-shuffle reduce only ----
        float rm0 = -1e30f, rm1 = -1e30f;
#pragma unroll
        for (int nt = 0; nt < 8; nt++) {
            rm0 = fmaxf(rm0, fmaxf(sacc[nt][0], sacc[nt][1]));
            rm1 = fmaxf(rm1, fmaxf(sacc[nt][2], sacc[nt][3]));
        }
        rm0 = fmaxf(rm0, __shfl_xor_sync(0xffffffffu, rm0, 1));
        rm0 = fmaxf(rm0, __shfl_xor_sync(0xffffffffu, rm0, 2));
        rm1 = fmaxf(rm1, __shfl_xor_sync(0xffffffffu, rm1, 1));
        rm1 = fmaxf(rm1, __shfl_xor_sync(0xffffffffu, rm1, 2));
        const float mn0 = fmaxf(mrow0, rm0);
        const float mn1 = fmaxf(mrow1, rm1);
        const float al0 = __expf(mrow0 - mn0);
        const float al1 = __expf(mrow1 - mn1);
        mrow0 = mn0;
        mrow1 = mn1;

        float sum0 = 0.f, sum1 = 0.f;
#pragma unroll
        for (int nt = 0; nt < 8; nt++) {
            sacc[nt][0] = __expf(sacc[nt][0] - mn0);
            sacc[nt][1] = __expf(sacc[nt][1] - mn0);
            sacc[nt][2] = __expf(sacc[nt][2] - mn1);
            sacc[nt][3] = __expf(sacc[nt][3] - mn1);
            sum0 += sacc[nt][0] + sacc[nt][1];
            sum1 += sacc[nt][2] + sacc[nt][3];
        }
        sum0 += __shfl_xor_sync(0xffffffffu, sum0, 1);
        sum0 += __shfl_xor_sync(0xffffffffu, sum0, 2);
        sum1 += __shfl_xor_sync(0xffffffffu, sum1, 1);
        sum1 += __shfl_xor_sync(0xffffffffu, sum1, 2);
        lrow0 = lrow0 * al0 + sum0;
        lrow1 = lrow1 * al1 + sum1;

        // rescale O only when some row's max actually moved (exp(0)==1 exactly)
        if (__ballot_sync(0xffffffffu, (al0 != 1.0f) || (al1 != 1.0f))) {
#pragma unroll
            for (int nt = 0; nt < 32; nt++) {
                oacc[nt][0] *= al0;
                oacc[nt][1] *= al0;
                oacc[nt][2] *= al1;
                oacc[nt][3] *= al1;
            }
        }

        // ---- O += P V : single-term, P fp16 from registers, V fp16 in SMEM ----
#pragma unroll
        for (int kc = 0; kc < 4; kc++) {
            unsigned ahh[4];
            ahh[0] = h2u(__floats2half2_rn(sacc[2 * kc][0],     sacc[2 * kc][1]));
            ahh[1] = h2u(__floats2half2_rn(sacc[2 * kc][2],     sacc[2 * kc][3]));
            ahh[2] = h2u(__floats2half2_rn(sacc[2 * kc + 1][0], sacc[2 * kc + 1][1]));
            ahh[3] = h2u(__floats2half2_rn(sacc[2 * kc + 1][2], sacc[2 * kc + 1][3]));
            const int cV = 2 * kc + bh;      // 0..7
            const unsigned voff = tr * 128 + (((cV ^ brx) & 7) << 4);
#pragma unroll
            for (int nb = 0; nb < 16; nb++) {
                unsigned vh4[4];
                ldsm_x4(vh4, vb + nb * 2048 + voff);
                mma16816(oacc[2 * nb],     ahh, vh4);
                mma16816(oacc[2 * nb + 1], ahh, vh4 + 2);
            }
        }
    }

    // ---- epilogue: normalize, two-pass SMEM transpose, residual add ----
    const float inv0 = 1.0f / lrow0;
    const float inv1 = 1.0f / lrow1;
#pragma unroll
    for (int nt = 0; nt < 32; nt++) {
        oacc[nt][0] *= inv0;
        oacc[nt][1] *= inv0;
        oacc[nt][2] *= inv1;
        oacc[nt][3] *= inv1;
    }

    float* stg = (float*)smc;    // [128 s][132] fp32 = 67584 B, tiles are dead
    const int cl0 = tid & 127;
    const int sg  = tid >> 7;    // 0,1 : s-half
    for (int pass = 0; pass < 2; pass++) {
        __syncthreads();
#pragma unroll
        for (int nt2 = 0; nt2 < 16; nt2++) {
            int nt = pass * 16 + nt2;
            int cl = nt2 * 8 + 2 * q3;
            *(float2*)&stg[(m0 + rq) * 132 + cl] =
                make_float2(oacc[nt][0], oacc[nt][1]);
            *(float2*)&stg[(m0 + rq + 8) * 132 + cl] =
                make_float2(oacc[nt][2], oacc[nt][3]);
        }
        __syncthreads();
        int c = pass * 128 + cl0;
        const float* xb = x   + ((size_t)n * CIN + c) * SQ + s0 + sg * 64;
        float*       ob = out + ((size_t)n * CIN + c) * SQ + s0 + sg * 64;
#pragma unroll
        for (int ss = 0; ss < 64; ss += 4) {
            float4 xv = *(const float4*)&xb[ss];
            float4 r;
            r.x = xv.x + stg[(sg * 64 + ss + 0) * 132 + cl0];
            r.y = xv.y + stg[(sg * 64 + ss + 1) * 132 + cl0];
            r.z = xv.z + stg[(sg * 64 + ss + 2) * 132 + cl0];
            r.w = xv.w + stg[(sg * 64 + ss + 3) * 132 + cl0];
            *(float4*)&ob[ss] = r;
        }
    }
}

// ---------------------------------------------------------------------------
extern "C" void kernel_launch(void* const* d_in, const int* in_sizes, int n_in,
                              void* d_out, int out_size)
{
    const float* x  = (const float*)d_in[0];   // [8,256,64,64]
    const float* tw = (const float*)d_in[1];   // [128,256]
    const float* pw = (const float*)d_in[2];   // [128,256]
    float* out = (float*)d_out;

    cudaFuncSetAttribute(flash_tc,
                         cudaFuncAttributeMaxDynamicSharedMemorySize, SM_TOTAL);

    proj_kernel<<<dim3(64, 8), 256>>>(x, tw, pw);
    flash_tc<<<dim3(32, 8), 256, SM_TOTAL>>>(x, out);
}